// round 13
// baseline (speedup 1.0000x reference)
#include <cuda_runtime.h>
#include <cuda_bf16.h>
#include <cuda_fp16.h>
#include <stdint.h>

#define NN 50000
#define NE 800000
#define INF 128
#define HID 64
#define S ((size_t)NN * HID)

// packed dual fp32 FMA (sm_103a)
#define FMA_F32X2(d, a, b, c) \
    asm("fma.rn.f32x2 %0, %1, %2, %3;" : "=l"(d) : "l"(a), "l"(b), "l"(c))

__device__ __forceinline__ float x2lo(unsigned long long v) {
    return __uint_as_float((unsigned)(v & 0xffffffffull));
}
__device__ __forceinline__ float x2hi(unsigned long long v) {
    return __uint_as_float((unsigned)(v >> 32));
}

// ---------------- scratch ----------------
// fbuf slots: 0=fo0 1=fs0 2=fo1 3=fs1
__device__ float d_fbuf[(size_t)4 * NN * HID];
__device__ __align__(16) __half d_gh[(size_t)4 * NN * HID];
__device__ float d_dinv[2 * NN];
__device__ int   d_cnt [2 * NN];          // static-zero; scan_k re-zeroes each pass
__device__ int   d_cur [2 * NN];
__device__ int   d_rs  [2 * (NN + 1)];
__device__ int   d_csr [2 * NE];
__device__ float d_weff[16384];   // tail layer-1 weights [s(4)][kp(32)][c(64)][2]

// ---------------- degree histogram ----------------
__global__ void count_k(const int4* __restrict__ d0, const int4* __restrict__ d1,
                        int* __restrict__ cnt, int ne4) {
    int i = blockIdx.x * blockDim.x + threadIdx.x;
    if (i >= 2 * ne4) return;
    int b = (i >= ne4) ? 1 : 0;
    int4 v = b ? d1[i - ne4] : d0[i];
    int* c = cnt + b * NN;
    atomicAdd(&c[v.x], 1);
    atomicAdd(&c[v.y], 1);
    atomicAdd(&c[v.z], 1);
    atomicAdd(&c[v.w], 1);
}

// ---------------- exclusive scan + dinv + cur init; zeroes cnt for next replay ----------------
__global__ void scan_k(int* __restrict__ cntA, int* __restrict__ rsA,
                       float* __restrict__ dvA, int* __restrict__ curA, int n) {
    int*   cnt = cntA + blockIdx.x * NN;
    int*   rs  = rsA  + blockIdx.x * (NN + 1);
    float* dv  = dvA  + blockIdx.x * NN;
    int*   cur = curA + blockIdx.x * NN;
    __shared__ int wsum[32];
    __shared__ int carry_s;
    int tid = threadIdx.x, lane = tid & 31, wid = tid >> 5;
    if (tid == 0) carry_s = 0;
    __syncthreads();
    for (int base = 0; base < n; base += 1024) {
        int i = base + tid;
        int v = (i < n) ? cnt[i] : 0;
        int x = v;
        #pragma unroll
        for (int d = 1; d < 32; d <<= 1) {
            int t = __shfl_up_sync(0xffffffffu, x, d);
            if (lane >= d) x += t;
        }
        if (lane == 31) wsum[wid] = x;
        __syncthreads();
        if (wid == 0) {
            int w = wsum[lane];
            int y = w;
            #pragma unroll
            for (int d = 1; d < 32; d <<= 1) {
                int t = __shfl_up_sync(0xffffffffu, y, d);
                if (lane >= d) y += t;
            }
            wsum[lane] = y - w;
        }
        __syncthreads();
        int excl = x - v + wsum[wid] + carry_s;
        if (i < n) {
            rs[i]  = excl;
            cur[i] = excl;
            dv[i]  = rsqrtf((float)(v > 0 ? v : 1));
            cnt[i] = 0;                      // reset for next graph replay
        }
        __syncthreads();
        if (tid == 1023) carry_s = excl + v;
        __syncthreads();
    }
    if (threadIdx.x == 0) rs[n] = carry_s;
}

// ---------------- CSR fill ----------------
__global__ void fill_k(const int4* __restrict__ s0, const int4* __restrict__ s1,
                       const int4* __restrict__ d0, const int4* __restrict__ d1,
                       int* __restrict__ cur, int* __restrict__ csr, int ne4) {
    int i = blockIdx.x * blockDim.x + threadIdx.x;
    if (i >= 2 * ne4) return;
    int b = (i >= ne4) ? 1 : 0;
    int j = i - b * ne4;
    int4 dd = b ? d1[j] : d0[j];
    int4 sv = b ? s1[j] : s0[j];
    int* cu = cur + b * NN;
    int* cs = csr + (size_t)b * NE;
    cs[atomicAdd(&cu[dd.x], 1)] = sv.x;
    cs[atomicAdd(&cu[dd.y], 1)] = sv.y;
    cs[atomicAdd(&cu[dd.z], 1)] = sv.z;
    cs[atomicAdd(&cu[dd.w], 1)] = sv.w;
}

// ---------------- input GEMM + relu ----------------
__global__ void __launch_bounds__(256, 4) gemm_relu_k(
        const float* __restrict__ X0, const float* __restrict__ X1,
        const float* __restrict__ W0g, const float* __restrict__ W1g,
        const float* __restrict__ b0, const float* __restrict__ b1,
        float* __restrict__ f0base, int n) {
    __shared__ float Xs[64 * 64];    // 16 KB (one 64-k chunk)
    __shared__ float Wpc[4096];      // 16 KB [32kp][64c][2]
    int by = blockIdx.y;
    const float* X = by ? X1 : X0;
    const float* W = by ? W1g : W0g;
    const float* b = by ? b1 : b0;
    float* H = f0base + (size_t)by * S;

    int tid = threadIdx.x;
    int cp = tid & 15;
    int ng = tid >> 4;
    int nb = blockIdx.x * 64;
    int nvalid = n - nb; if (nvalid > 64) nvalid = 64;

    unsigned long long acc[4][4];
    #pragma unroll
    for (int j = 0; j < 4; j++)
        #pragma unroll
        for (int q = 0; q < 4; q++) acc[j][q] = 0ull;

    #pragma unroll
    for (int ch = 0; ch < 2; ch++) {
        __syncthreads();
        for (int i4 = tid; i4 < 1024; i4 += 256) {
            int node = i4 >> 4, f = i4 & 15;
            float4 v = make_float4(0.f, 0.f, 0.f, 0.f);
            if (node < nvalid)
                v = *(const float4*)(X + (size_t)(nb + node) * 128 + ch * 64 + f * 4);
            ((float4*)Xs)[i4] = v;
        }
        for (int i = tid; i < 4096; i += 256) {
            int j = i & 1, c = (i >> 1) & 63, kp = i >> 7;
            Wpc[i] = W[(size_t)(ch * 64 + 2 * kp + j) * 64 + c];
        }
        __syncthreads();
        #pragma unroll 4
        for (int kp2 = 0; kp2 < 16; kp2++) {
            float4 x4[4];
            #pragma unroll
            for (int j = 0; j < 4; j++)
                x4[j] = *(const float4*)&Xs[(ng * 4 + j) * 64 + 4 * kp2];
            #pragma unroll
            for (int h = 0; h < 2; h++) {
                int kp = 2 * kp2 + h;
                unsigned long long w[4];
                #pragma unroll
                for (int q = 0; q < 4; q++)
                    w[q] = *(const unsigned long long*)&Wpc[(kp * 64 + cp + 16 * q) * 2];
                #pragma unroll
                for (int j = 0; j < 4; j++) {
                    unsigned long long x = ((const unsigned long long*)&x4[j])[h];
                    #pragma unroll
                    for (int q = 0; q < 4; q++) FMA_F32X2(acc[j][q], x, w[q], acc[j][q]);
                }
            }
        }
    }

    #pragma unroll
    for (int j = 0; j < 4; j++) {
        int node = nb + ng * 4 + j;
        if (node < n) {
            #pragma unroll
            for (int q = 0; q < 4; q++) {
                int col = cp + 16 * q;
                float v = x2lo(acc[j][q]) + x2hi(acc[j][q]) + b[col];
                H[(size_t)node * 64 + col] = v > 0.f ? v : 0.f;
            }
        }
    }
}

// ---------------- g(fp16) = H * dinv ----------------
__global__ void scale_k(const float4* __restrict__ H, const float* __restrict__ dinv_all,
                        uint4* __restrict__ G, int total) {
    int i = blockIdx.x * blockDim.x + threadIdx.x;
    if (i >= total) return;
    float dv = dinv_all[i >> 3];
    float4 a = H[2 * i], b = H[2 * i + 1];
    __half2 h0 = __floats2half2_rn(a.x * dv, a.y * dv);
    __half2 h1 = __floats2half2_rn(a.z * dv, a.w * dv);
    __half2 h2 = __floats2half2_rn(b.x * dv, b.y * dv);
    __half2 h3 = __floats2half2_rn(b.z * dv, b.w * dv);
    uint4 o;
    o.x = *(unsigned*)&h0; o.y = *(unsigned*)&h1;
    o.z = *(unsigned*)&h2; o.w = *(unsigned*)&h3;
    G[i] = o;
}

// ---------------- tail weight prep ----------------
__global__ void prep_k(const float* __restrict__ Wm1, float* __restrict__ weff) {
    int i = blockIdx.x * blockDim.x + threadIdx.x;
    if (i >= 16384) return;
    int j = i & 1, c = (i >> 1) & 63, kpg = i >> 7;
    int s = kpg >> 5;
    int kk = 2 * (kpg & 31) + j;
    float v;
    if (s < 3)
        v = Wm1[(s * 64 + kk) * 64 + c];
    else
        v = Wm1[(192 + kk) * 64 + c] + Wm1[(256 + kk) * 64 + c] +
            Wm1[(320 + kk) * 64 + c];
    weff[i] = v;
}

// ---------------- prop step 1: f1 = f0 - dinv*gather(ga); g1 = f1*dinv ----------------
// Fully predicated gather (no break) -> all 8 LDG.128 batches in flight; f prefetched.
__global__ void prop_k(const __half* __restrict__ gin, const float* __restrict__ fin,
                       float* __restrict__ fout, __half* __restrict__ gout,
                       const float* __restrict__ dinv_all, const int* __restrict__ rs_all,
                       const int* __restrict__ csr_all, int n) {
    int gw = (blockIdx.x * blockDim.x + threadIdx.x) >> 5;
    int lane = threadIdx.x & 31;
    if (gw >= 2 * n) return;
    int b = (gw >= n) ? 1 : 0;
    int w = gw - b * n;
    const __half* gp  = gin + (size_t)b * S;
    const int*    rs  = rs_all + b * (NN + 1);
    const int*    csr = csr_all + (size_t)b * NE;
    int beg = rs[w], end = rs[w + 1];

    int grp = lane >> 3;
    int sub = lane & 7;

    // prefetch (all lanes; 8 distinct addrs -> L1 broadcast)
    float dvv = dinv_all[b * NN + w];
    size_t roff = (size_t)b * S + (size_t)w * 64 + sub * 8;
    const float4* f4 = (const float4*)(fin + roff);
    float4 fv0 = f4[0], fv1 = f4[1];

    float a[8];
    #pragma unroll
    for (int i = 0; i < 8; i++) a[i] = 0.f;

    for (int base = beg; base < end; base += 32) {
        int idx = base + lane;
        int sreg = (idx < end) ? __ldg(&csr[idx]) : 0;
        int cnt = end - base;
        if (cnt > 32) cnt = 32;
        #pragma unroll
        for (int tb = 0; tb < 8; tb++) {
            int t = tb * 4 + grp;
            int ss = __shfl_sync(0xffffffffu, sreg, t);
            if (t < cnt) {
                uint4 v = *(const uint4*)(gp + (size_t)ss * 64 + sub * 8);
                const __half2* h = (const __half2*)&v;
                #pragma unroll
                for (int q = 0; q < 4; q++) {
                    float2 f = __half22float2(h[q]);
                    a[2 * q]     += f.x;
                    a[2 * q + 1] += f.y;
                }
            }
        }
    }

    #pragma unroll
    for (int i = 0; i < 8; i++) {
        a[i] += __shfl_xor_sync(0xffffffffu, a[i], 8);
        a[i] += __shfl_xor_sync(0xffffffffu, a[i], 16);
    }

    if (lane < 8) {
        float4 o0, o1;
        o0.x = fv0.x - a[0] * dvv;
        o0.y = fv0.y - a[1] * dvv;
        o0.z = fv0.z - a[2] * dvv;
        o0.w = fv0.w - a[3] * dvv;
        o1.x = fv1.x - a[4] * dvv;
        o1.y = fv1.y - a[5] * dvv;
        o1.z = fv1.z - a[6] * dvv;
        o1.w = fv1.w - a[7] * dvv;
        float4* fo = (float4*)(fout + roff);
        fo[0] = o0;
        fo[1] = o1;
        __half2 h0 = __floats2half2_rn(o0.x * dvv, o0.y * dvv);
        __half2 h1 = __floats2half2_rn(o0.z * dvv, o0.w * dvv);
        __half2 h2 = __floats2half2_rn(o1.x * dvv, o1.y * dvv);
        __half2 h3 = __floats2half2_rn(o1.z * dvv, o1.w * dvv);
        uint4 gv;
        gv.x = *(unsigned*)&h0; gv.y = *(unsigned*)&h1;
        gv.z = *(unsigned*)&h2; gv.w = *(unsigned*)&h3;
        *(uint4*)(gout + roff) = gv;
    }
}

// ---------------- prop step 2 + combine: write h_all directly ----------------
__global__ void prop2h_k(const __half* __restrict__ gin, const float* __restrict__ f1base,
                         const float* __restrict__ f0base,
                         const float* __restrict__ dinv_all, const int* __restrict__ rs_all,
                         const int* __restrict__ csr_all, float* __restrict__ out, int n) {
    int gw = (blockIdx.x * blockDim.x + threadIdx.x) >> 5;
    int lane = threadIdx.x & 31;
    if (gw >= 2 * n) return;
    int b = (gw >= n) ? 1 : 0;
    int w = gw - b * n;
    const __half* gp  = gin + (size_t)b * S;
    const int*    rs  = rs_all + b * (NN + 1);
    const int*    csr = csr_all + (size_t)b * NE;
    int beg = rs[w], end = rs[w + 1];

    int grp = lane >> 3;
    int sub = lane & 7;

    // prefetch (all lanes; broadcast addresses)
    float dvv = dinv_all[b * NN + w];
    size_t roff = (size_t)b * S + (size_t)w * 64 + sub * 8;
    const float4* f14 = (const float4*)(f1base + roff);
    const float4* f04 = (const float4*)(f0base + roff);
    float4 f1v[2] = {f14[0], f14[1]};
    float4 f0v[2] = {f04[0], f04[1]};

    float a[8];
    #pragma unroll
    for (int i = 0; i < 8; i++) a[i] = 0.f;

    for (int base = beg; base < end; base += 32) {
        int idx = base + lane;
        int sreg = (idx < end) ? __ldg(&csr[idx]) : 0;
        int cnt = end - base;
        if (cnt > 32) cnt = 32;
        #pragma unroll
        for (int tb = 0; tb < 8; tb++) {
            int t = tb * 4 + grp;
            int ss = __shfl_sync(0xffffffffu, sreg, t);
            if (t < cnt) {
                uint4 v = *(const uint4*)(gp + (size_t)ss * 64 + sub * 8);
                const __half2* h = (const __half2*)&v;
                #pragma unroll
                for (int q = 0; q < 4; q++) {
                    float2 f = __half22float2(h[q]);
                    a[2 * q]     += f.x;
                    a[2 * q + 1] += f.y;
                }
            }
        }
    }

    #pragma unroll
    for (int i = 0; i < 8; i++) {
        a[i] += __shfl_xor_sync(0xffffffffu, a[i], 8);
        a[i] += __shfl_xor_sync(0xffffffffu, a[i], 16);
    }

    if (lane < 8) {
        float* op = out + (size_t)w * 384 + sub * 8;
        #pragma unroll
        for (int h = 0; h < 2; h++) {
            float f2v[4];
            const float* f1p = (const float*)&f1v[h];
            const float* f0p = (const float*)&f0v[h];
            #pragma unroll
            for (int q = 0; q < 4; q++) f2v[q] = f1p[q] - a[4 * h + q] * dvv;
            float4 s0, s1, s2;
            if (b == 0) {
                #pragma unroll
                for (int q = 0; q < 4; q++) {
                    ((float*)&s0)[q] = 3.f * f0p[q] - 3.f * f1p[q] + 0.75f * f2v[q];
                    ((float*)&s1)[q] = 3.f * f1p[q] - 1.5f * f2v[q];
                    ((float*)&s2)[q] = 0.75f * f2v[q];
                }
                *(float4*)(op + h * 4)       = s0;
                *(float4*)(op + 64 + h * 4)  = s1;
                *(float4*)(op + 128 + h * 4) = s2;
            } else {
                #pragma unroll
                for (int q = 0; q < 4; q++)
                    ((float*)&s0)[q] = 4.f * (f0p[q] + f1p[q] + f2v[q]);
                *(float4*)(op + 192 + h * 4) = s0;
                *(float4*)(op + 256 + h * 4) = s0;
                *(float4*)(op + 320 + h * 4) = s0;
            }
        }
    }
}

// ---------------- tail MLP: reads h_all segs 0..3, writes logits ----------------
__global__ void __launch_bounds__(256) tail_k(
        const float* __restrict__ hall, const float* __restrict__ weffp,
        const float* __restrict__ bm1, const float* __restrict__ Wm2,
        const float* __restrict__ bm2, float* __restrict__ logits, int n) {
    __shared__ float Xs[4][32 * 64];   // 32 KB
    __shared__ float Wpc[4096];        // 16 KB
    __shared__ float Zs[32 * 68];      // 8.5 KB
    int tid = threadIdx.x;
    int cp = tid & 15, ng = tid >> 4;
    int nb = blockIdx.x * 32;

    for (int t = tid; t < 2048; t += 256) {
        int s = t >> 9;
        int i4 = t & 511;
        int node = i4 >> 4, f = i4 & 15;
        float4 v = make_float4(0.f, 0.f, 0.f, 0.f);
        if (nb + node < n)
            v = *(const float4*)(hall + (size_t)(nb + node) * 384 + s * 64 + f * 4);
        ((float4*)Xs[s])[i4] = v;
    }

    unsigned long long acc[2][4];
    #pragma unroll
    for (int j = 0; j < 2; j++)
        #pragma unroll
        for (int q = 0; q < 4; q++) acc[j][q] = 0ull;

    #pragma unroll
    for (int s = 0; s < 4; s++) {
        __syncthreads();
        for (int i = tid; i < 4096; i += 256) Wpc[i] = weffp[s * 4096 + i];
        __syncthreads();
        #pragma unroll 4
        for (int kp2 = 0; kp2 < 16; kp2++) {
            float4 x4[2];
            #pragma unroll
            for (int j = 0; j < 2; j++)
                x4[j] = *(const float4*)&Xs[s][(ng * 2 + j) * 64 + 4 * kp2];
            #pragma unroll
            for (int h = 0; h < 2; h++) {
                int kp = 2 * kp2 + h;
                unsigned long long w[4];
                #pragma unroll
                for (int q = 0; q < 4; q++)
                    w[q] = *(const unsigned long long*)&Wpc[(kp * 64 + cp + 16 * q) * 2];
                #pragma unroll
                for (int j = 0; j < 2; j++) {
                    unsigned long long x = ((const unsigned long long*)&x4[j])[h];
                    #pragma unroll
                    for (int q = 0; q < 4; q++) FMA_F32X2(acc[j][q], x, w[q], acc[j][q]);
                }
            }
        }
    }
    __syncthreads();
    #pragma unroll
    for (int j = 0; j < 2; j++) {
        int node_l = ng * 2 + j;
        #pragma unroll
        for (int q = 0; q < 4; q++) {
            int col = cp + 16 * q;
            float z = x2lo(acc[j][q]) + x2hi(acc[j][q]) + bm1[col];
            Zs[node_l * 68 + col] = z > 0.f ? z : 0.f;
        }
    }
    __syncthreads();

    if (tid < 64) {
        int node = tid >> 1, jj = tid & 1;
        if (nb + node < n) {
            float sacc = bm2[jj];
            #pragma unroll 8
            for (int c = 0; c < 64; c++) sacc += Zs[node * 68 + c] * Wm2[c * 2 + jj];
            logits[(size_t)(nb + node) * 2 + jj] = sacc;
        }
    }
}

// ---------------- launch (single stream, deterministic order) ----------------
extern "C" void kernel_launch(void* const* d_in, const int* in_sizes, int n_in,
                              void* d_out, int out_size) {
    const float* x     = (const float*)d_in[0];
    const float* sim_x = (const float*)d_in[1];
    const int*   src   = (const int*)d_in[2];
    const int*   dst   = (const int*)d_in[3];
    const int*   ssrc  = (const int*)d_in[4];
    const int*   sdst  = (const int*)d_in[5];
    const float* W1o   = (const float*)d_in[6];
    const float* b1o   = (const float*)d_in[7];
    const float* W1s   = (const float*)d_in[8];
    const float* b1s   = (const float*)d_in[9];
    const float* Wm1   = (const float*)d_in[10];
    const float* bm1   = (const float*)d_in[11];
    const float* Wm2   = (const float*)d_in[12];
    const float* bm2   = (const float*)d_in[13];

    const int n = NN, ne = NE;

    float *fbuf, *dinv, *weff; __half* gh; int *cnt, *cur, *rs, *csr;
    cudaGetSymbolAddress((void**)&fbuf, d_fbuf);
    cudaGetSymbolAddress((void**)&gh,   d_gh);
    cudaGetSymbolAddress((void**)&dinv, d_dinv);
    cudaGetSymbolAddress((void**)&cnt,  d_cnt);
    cudaGetSymbolAddress((void**)&cur,  d_cur);
    cudaGetSymbolAddress((void**)&rs,   d_rs);
    cudaGetSymbolAddress((void**)&csr,  d_csr);
    cudaGetSymbolAddress((void**)&weff, d_weff);

    float*  f0base = fbuf + 0 * S;
    float*  f1base = fbuf + 2 * S;
    __half* gabase = gh;
    __half* gbbase = gh + 2 * S;

    float* out    = (float*)d_out;
    float* logits = out + (size_t)n * 384;

    int ne4 = ne / 4;
    int eb4 = (2 * ne4 + 255) / 256;
    int pb = (2 * n * 32 + 255) / 256;
    int total8 = (int)(2 * S / 8);

    // 1..3: CSR build (cnt is zeroed by previous scan_k / static init)
    count_k<<<eb4, 256>>>((const int4*)dst, (const int4*)sdst, cnt, ne4);
    scan_k<<<2, 1024>>>(cnt, rs, dinv, cur, n);
    fill_k<<<eb4, 256>>>((const int4*)src, (const int4*)ssrc,
                         (const int4*)dst, (const int4*)sdst, cur, csr, ne4);

    // 4: input GEMM
    dim3 gg((n + 63) / 64, 2);
    gemm_relu_k<<<gg, 256>>>(x, sim_x, W1o, W1s, b1o, b1s, f0base, n);

    // 5: g0 = relu * dinv (fp16)
    scale_k<<<(total8 + 255) / 256, 256>>>((const float4*)f0base, dinv,
                                           (uint4*)gabase, total8);

    // 6: prop step 1  (target of the ncu capture slot)
    prop_k<<<pb, 256>>>(gabase, f0base, f1base, gbbase, dinv, rs, csr, n);

    // 7: prop step 2 + combine -> h_all
    prop2h_k<<<pb, 256>>>(gbbase, f1base, f0base, dinv, rs, csr, out, n);

    // 8: tail weights, 9: tail MLP
    prep_k<<<64, 256>>>(Wm1, weff);
    tail_k<<<(n + 31) / 32, 256>>>(out, weff, bm1, Wm2, bm2, logits, n);
}

// round 14
// speedup vs baseline: 1.1000x; 1.1000x over previous
#include <cuda_runtime.h>
#include <cuda_bf16.h>
#include <cuda_fp16.h>
#include <stdint.h>

#define NN 50000
#define NE 800000
#define INF 128
#define HID 64
#define S ((size_t)NN * HID)

// packed dual fp32 FMA (sm_103a)
#define FMA_F32X2(d, a, b, c) \
    asm("fma.rn.f32x2 %0, %1, %2, %3;" : "=l"(d) : "l"(a), "l"(b), "l"(c))

__device__ __forceinline__ float x2lo(unsigned long long v) {
    return __uint_as_float((unsigned)(v & 0xffffffffull));
}
__device__ __forceinline__ float x2hi(unsigned long long v) {
    return __uint_as_float((unsigned)(v >> 32));
}

// ---------------- scratch ----------------
// fbuf slots (each S floats): 0=fo0 1=fs0 2=fo1 3=fs1 4=fo2 5=fs2
__device__ float d_fbuf[(size_t)6 * NN * HID];
__device__ __align__(16) __half d_gh[(size_t)4 * NN * HID];
__device__ float d_dinv[2 * NN];
__device__ int   d_cnt [2 * NN];          // static-zero; scan_k re-zeroes each pass
__device__ int   d_cur [2 * NN];
__device__ int   d_rs  [2 * (NN + 1)];
__device__ int   d_csr [2 * NE];
__device__ float d_weff[16384];   // folded tail layer-1 weights, interleaved [kp][c][2]

// ---------------- degree histogram ----------------
__global__ void count_k(const int4* __restrict__ d0, const int4* __restrict__ d1,
                        int* __restrict__ cnt, int ne4) {
    int i = blockIdx.x * blockDim.x + threadIdx.x;
    if (i >= 2 * ne4) return;
    int b = (i >= ne4) ? 1 : 0;
    int4 v = b ? d1[i - ne4] : d0[i];
    int* c = cnt + b * NN;
    atomicAdd(&c[v.x], 1);
    atomicAdd(&c[v.y], 1);
    atomicAdd(&c[v.z], 1);
    atomicAdd(&c[v.w], 1);
}

// ---------------- exclusive scan + dinv + cur init; zeroes cnt for next replay ----------------
__global__ void scan_k(int* __restrict__ cntA, int* __restrict__ rsA,
                       float* __restrict__ dvA, int* __restrict__ curA, int n) {
    int*   cnt = cntA + blockIdx.x * NN;
    int*   rs  = rsA  + blockIdx.x * (NN + 1);
    float* dv  = dvA  + blockIdx.x * NN;
    int*   cur = curA + blockIdx.x * NN;
    __shared__ int wsum[32];
    __shared__ int carry_s;
    int tid = threadIdx.x, lane = tid & 31, wid = tid >> 5;
    if (tid == 0) carry_s = 0;
    __syncthreads();
    for (int base = 0; base < n; base += 1024) {
        int i = base + tid;
        int v = (i < n) ? cnt[i] : 0;
        int x = v;
        #pragma unroll
        for (int d = 1; d < 32; d <<= 1) {
            int t = __shfl_up_sync(0xffffffffu, x, d);
            if (lane >= d) x += t;
        }
        if (lane == 31) wsum[wid] = x;
        __syncthreads();
        if (wid == 0) {
            int w = wsum[lane];
            int y = w;
            #pragma unroll
            for (int d = 1; d < 32; d <<= 1) {
                int t = __shfl_up_sync(0xffffffffu, y, d);
                if (lane >= d) y += t;
            }
            wsum[lane] = y - w;
        }
        __syncthreads();
        int excl = x - v + wsum[wid] + carry_s;
        if (i < n) {
            rs[i]  = excl;
            cur[i] = excl;
            dv[i]  = rsqrtf((float)(v > 0 ? v : 1));
            cnt[i] = 0;                      // reset for next graph replay
        }
        __syncthreads();
        if (tid == 1023) carry_s = excl + v;
        __syncthreads();
    }
    if (threadIdx.x == 0) rs[n] = carry_s;
}

// ---------------- CSR fill ----------------
__global__ void fill_k(const int4* __restrict__ s0, const int4* __restrict__ s1,
                       const int4* __restrict__ d0, const int4* __restrict__ d1,
                       int* __restrict__ cur, int* __restrict__ csr, int ne4) {
    int i = blockIdx.x * blockDim.x + threadIdx.x;
    if (i >= 2 * ne4) return;
    int b = (i >= ne4) ? 1 : 0;
    int j = i - b * ne4;
    int4 dd = b ? d1[j] : d0[j];
    int4 sv = b ? s1[j] : s0[j];
    int* cu = cur + b * NN;
    int* cs = csr + (size_t)b * NE;
    cs[atomicAdd(&cu[dd.x], 1)] = sv.x;
    cs[atomicAdd(&cu[dd.y], 1)] = sv.y;
    cs[atomicAdd(&cu[dd.z], 1)] = sv.z;
    cs[atomicAdd(&cu[dd.w], 1)] = sv.w;
}

// ---------------- input GEMM + relu (chunked Xs; 4 CTAs/SM reg cap) ----------------
__global__ void __launch_bounds__(256, 4) gemm_relu_k(
        const float* __restrict__ X0, const float* __restrict__ X1,
        const float* __restrict__ W0g, const float* __restrict__ W1g,
        const float* __restrict__ b0, const float* __restrict__ b1,
        float* __restrict__ f0base, int n) {
    __shared__ float Xs[64 * 64];    // 16 KB (one 64-k chunk)
    __shared__ float Wpc[4096];      // 16 KB [32kp][64c][2]
    int by = blockIdx.y;
    const float* X = by ? X1 : X0;
    const float* W = by ? W1g : W0g;
    const float* b = by ? b1 : b0;
    float* H = f0base + (size_t)by * S;

    int tid = threadIdx.x;
    int cp = tid & 15;
    int ng = tid >> 4;        // 0..15, 4 nodes each
    int nb = blockIdx.x * 64;
    int nvalid = n - nb; if (nvalid > 64) nvalid = 64;

    unsigned long long acc[4][4];
    #pragma unroll
    for (int j = 0; j < 4; j++)
        #pragma unroll
        for (int q = 0; q < 4; q++) acc[j][q] = 0ull;

    #pragma unroll
    for (int ch = 0; ch < 2; ch++) {
        __syncthreads();
        for (int i4 = tid; i4 < 1024; i4 += 256) {
            int node = i4 >> 4, f = i4 & 15;
            float4 v = make_float4(0.f, 0.f, 0.f, 0.f);
            if (node < nvalid)
                v = *(const float4*)(X + (size_t)(nb + node) * 128 + ch * 64 + f * 4);
            ((float4*)Xs)[i4] = v;
        }
        for (int i = tid; i < 4096; i += 256) {
            int j = i & 1, c = (i >> 1) & 63, kp = i >> 7;
            Wpc[i] = W[(size_t)(ch * 64 + 2 * kp + j) * 64 + c];
        }
        __syncthreads();
        #pragma unroll 4
        for (int kp2 = 0; kp2 < 16; kp2++) {
            float4 x4[4];
            #pragma unroll
            for (int j = 0; j < 4; j++)
                x4[j] = *(const float4*)&Xs[(ng * 4 + j) * 64 + 4 * kp2];
            #pragma unroll
            for (int h = 0; h < 2; h++) {
                int kp = 2 * kp2 + h;
                unsigned long long w[4];
                #pragma unroll
                for (int q = 0; q < 4; q++)
                    w[q] = *(const unsigned long long*)&Wpc[(kp * 64 + cp + 16 * q) * 2];
                #pragma unroll
                for (int j = 0; j < 4; j++) {
                    unsigned long long x = ((const unsigned long long*)&x4[j])[h];
                    #pragma unroll
                    for (int q = 0; q < 4; q++) FMA_F32X2(acc[j][q], x, w[q], acc[j][q]);
                }
            }
        }
    }

    #pragma unroll
    for (int j = 0; j < 4; j++) {
        int node = nb + ng * 4 + j;
        if (node < n) {
            #pragma unroll
            for (int q = 0; q < 4; q++) {
                int col = cp + 16 * q;
                float v = x2lo(acc[j][q]) + x2hi(acc[j][q]) + b[col];
                H[(size_t)node * 64 + col] = v > 0.f ? v : 0.f;
            }
        }
    }
}

// ---------------- g(fp16) = H * dinv ----------------
__global__ void scale_k(const float4* __restrict__ H, const float* __restrict__ dinv_all,
                        uint4* __restrict__ G, int total) {
    int i = blockIdx.x * blockDim.x + threadIdx.x;
    if (i >= total) return;
    float dv = dinv_all[i >> 3];
    float4 a = H[2 * i], b = H[2 * i + 1];
    __half2 h0 = __floats2half2_rn(a.x * dv, a.y * dv);
    __half2 h1 = __floats2half2_rn(a.z * dv, a.w * dv);
    __half2 h2 = __floats2half2_rn(b.x * dv, b.y * dv);
    __half2 h3 = __floats2half2_rn(b.z * dv, b.w * dv);
    uint4 o;
    o.x = *(unsigned*)&h0; o.y = *(unsigned*)&h1;
    o.z = *(unsigned*)&h2; o.w = *(unsigned*)&h3;
    G[i] = o;
}

// ---------------- tail weight prep (combine-fold, interleaved) ----------------
// basis (f0, f1, f2, ssum): 3W0 | -3W0+3W1 | 0.75W0-1.5W1+0.75W2 | 4(W3+W4+W5)
__global__ void prep_k(const float* __restrict__ Wm1, float* __restrict__ weff) {
    int i = blockIdx.x * blockDim.x + threadIdx.x;
    if (i >= 16384) return;
    int j = i & 1, c = (i >> 1) & 63, kpg = i >> 7;   // kpg 0..127
    int s = kpg >> 5;
    int kk = 2 * (kpg & 31) + j;                     // 0..63 within segment
    float w0 = Wm1[kk * 64 + c];
    float w1 = Wm1[(64 + kk) * 64 + c];
    float w2 = Wm1[(128 + kk) * 64 + c];
    float v;
    if (s == 0)      v = 3.f * w0;
    else if (s == 1) v = -3.f * w0 + 3.f * w1;
    else if (s == 2) v = 0.75f * w0 - 1.5f * w1 + 0.75f * w2;
    else v = 4.f * (Wm1[(192 + kk) * 64 + c] + Wm1[(256 + kk) * 64 + c] +
                    Wm1[(320 + kk) * 64 + c]);
    weff[i] = v;
}

// ---------------- propagation (predicated gather + prefetch), both branches ----------------
__global__ void prop_k(const __half* __restrict__ gin, const float* __restrict__ fin,
                       float* __restrict__ fout, __half* __restrict__ gout,
                       const float* __restrict__ dinv_all, const int* __restrict__ rs_all,
                       const int* __restrict__ csr_all, int n, int writeG) {
    int gw = (blockIdx.x * blockDim.x + threadIdx.x) >> 5;
    int lane = threadIdx.x & 31;
    if (gw >= 2 * n) return;
    int b = (gw >= n) ? 1 : 0;
    int w = gw - b * n;
    const __half* gp  = gin + (size_t)b * S;
    const int*    rs  = rs_all + b * (NN + 1);
    const int*    csr = csr_all + (size_t)b * NE;
    int beg = rs[w], end = rs[w + 1];

    int grp = lane >> 3;          // edge slot within 4-edge batch
    int sub = lane & 7;           // 16-B piece within 128-B row

    // prefetch node-local operands (all lanes; 8 distinct addrs -> broadcast)
    float dvv = dinv_all[b * NN + w];
    size_t roff = (size_t)b * S + (size_t)w * 64 + sub * 8;
    const float4* f4 = (const float4*)(fin + roff);
    float4 fv0 = f4[0], fv1 = f4[1];

    float a[8];
    #pragma unroll
    for (int i = 0; i < 8; i++) a[i] = 0.f;

    for (int base = beg; base < end; base += 32) {
        int idx = base + lane;
        int sreg = (idx < end) ? __ldg(&csr[idx]) : 0;
        int cnt = end - base;
        if (cnt > 32) cnt = 32;
        #pragma unroll
        for (int tb = 0; tb < 8; tb++) {
            int t = tb * 4 + grp;
            int ss = __shfl_sync(0xffffffffu, sreg, t);
            if (t < cnt) {
                uint4 v = *(const uint4*)(gp + (size_t)ss * 64 + sub * 8);
                const __half2* h = (const __half2*)&v;
                #pragma unroll
                for (int q = 0; q < 4; q++) {
                    float2 f = __half22float2(h[q]);
                    a[2 * q]     += f.x;
                    a[2 * q + 1] += f.y;
                }
            }
        }
    }

    #pragma unroll
    for (int i = 0; i < 8; i++) {
        a[i] += __shfl_xor_sync(0xffffffffu, a[i], 8);
        a[i] += __shfl_xor_sync(0xffffffffu, a[i], 16);
    }

    if (lane < 8) {
        float4 o0, o1;
        o0.x = fv0.x - a[0] * dvv;
        o0.y = fv0.y - a[1] * dvv;
        o0.z = fv0.z - a[2] * dvv;
        o0.w = fv0.w - a[3] * dvv;
        o1.x = fv1.x - a[4] * dvv;
        o1.y = fv1.y - a[5] * dvv;
        o1.z = fv1.z - a[6] * dvv;
        o1.w = fv1.w - a[7] * dvv;
        float4* fo = (float4*)(fout + roff);
        fo[0] = o0;
        fo[1] = o1;
        if (writeG) {
            __half2 h0 = __floats2half2_rn(o0.x * dvv, o0.y * dvv);
            __half2 h1 = __floats2half2_rn(o0.z * dvv, o0.w * dvv);
            __half2 h2 = __floats2half2_rn(o1.x * dvv, o1.y * dvv);
            __half2 h3 = __floats2half2_rn(o1.z * dvv, o1.w * dvv);
            uint4 gv;
            gv.x = *(unsigned*)&h0; gv.y = *(unsigned*)&h1;
            gv.z = *(unsigned*)&h2; gv.w = *(unsigned*)&h3;
            *(uint4*)(gout + roff) = gv;
        }
    }
}

// ---------------- fused tail: combine -> h_all + 2-layer MLP ----------------
// 32 nodes/block, 256 thr; thread: 2 nodes x 4 cols.
__global__ void __launch_bounds__(256) tail_k(
        const float* __restrict__ fbuf, const float* __restrict__ weffp,
        const float* __restrict__ bm1, const float* __restrict__ Wm2,
        const float* __restrict__ bm2,
        float* __restrict__ out, float* __restrict__ logits, int n) {
    __shared__ float Xs[4][32 * 64];   // 32 KB
    __shared__ float Wpc[4096];        // 16 KB
    __shared__ float Zs[32 * 68];      // 8.5 KB
    int tid = threadIdx.x;
    int cp = tid & 15, ng = tid >> 4;  // ng 0..15, 2 nodes each
    int nb = blockIdx.x * 32;

    const float* fo0 = fbuf + 0 * S;
    const float* fs0 = fbuf + 1 * S;
    const float* fo1 = fbuf + 2 * S;
    const float* fs1 = fbuf + 3 * S;
    const float* fo2 = fbuf + 4 * S;
    const float* fs2 = fbuf + 5 * S;

    int lim4 = (n - nb) * 16;
    if (lim4 > 512) lim4 = 512;
    for (int i4 = tid; i4 < 512; i4 += 256) {
        float4 z = make_float4(0.f, 0.f, 0.f, 0.f);
        float4 v0 = z, v1 = z, v2 = z, vs = z;
        if (i4 < lim4) {
            size_t off = (size_t)nb * 16 + i4;
            v0 = ((const float4*)fo0)[off];
            v1 = ((const float4*)fo1)[off];
            v2 = ((const float4*)fo2)[off];
            float4 u0 = ((const float4*)fs0)[off];
            float4 u1 = ((const float4*)fs1)[off];
            float4 u2 = ((const float4*)fs2)[off];
            vs.x = u0.x + u1.x + u2.x;
            vs.y = u0.y + u1.y + u2.y;
            vs.z = u0.z + u1.z + u2.z;
            vs.w = u0.w + u1.w + u2.w;
        }
        ((float4*)Xs[0])[i4] = v0;
        ((float4*)Xs[1])[i4] = v1;
        ((float4*)Xs[2])[i4] = v2;
        ((float4*)Xs[3])[i4] = vs;
    }
    __syncthreads();

    // h_all write (float4): 32 nodes x 96 float4
    int limo4 = (n - nb) * 96;
    if (limo4 > 3072) limo4 = 3072;
    for (int i4 = tid; i4 < limo4; i4 += 256) {
        int node_l = i4 / 96;
        int c4 = i4 - node_l * 96;
        int seg = c4 >> 4, cc4 = c4 & 15;
        int xi4 = node_l * 16 + cc4;
        float4 v;
        if (seg == 0) {
            float4 a0 = ((const float4*)Xs[0])[xi4];
            float4 a1 = ((const float4*)Xs[1])[xi4];
            float4 a2 = ((const float4*)Xs[2])[xi4];
            v.x = 3.f * a0.x - 3.f * a1.x + 0.75f * a2.x;
            v.y = 3.f * a0.y - 3.f * a1.y + 0.75f * a2.y;
            v.z = 3.f * a0.z - 3.f * a1.z + 0.75f * a2.z;
            v.w = 3.f * a0.w - 3.f * a1.w + 0.75f * a2.w;
        } else if (seg == 1) {
            float4 a1 = ((const float4*)Xs[1])[xi4];
            float4 a2 = ((const float4*)Xs[2])[xi4];
            v.x = 3.f * a1.x - 1.5f * a2.x;
            v.y = 3.f * a1.y - 1.5f * a2.y;
            v.z = 3.f * a1.z - 1.5f * a2.z;
            v.w = 3.f * a1.w - 1.5f * a2.w;
        } else if (seg == 2) {
            float4 a2 = ((const float4*)Xs[2])[xi4];
            v.x = 0.75f * a2.x; v.y = 0.75f * a2.y;
            v.z = 0.75f * a2.z; v.w = 0.75f * a2.w;
        } else {
            float4 a3 = ((const float4*)Xs[3])[xi4];
            v.x = 4.f * a3.x; v.y = 4.f * a3.y;
            v.z = 4.f * a3.z; v.w = 4.f * a3.w;
        }
        ((float4*)(out + (size_t)nb * 384))[i4] = v;
    }

    // layer 1 (K = 4 x 64, folded weights on basis f0,f1,f2,ssum)
    unsigned long long acc[2][4];
    #pragma unroll
    for (int j = 0; j < 2; j++)
        #pragma unroll
        for (int q = 0; q < 4; q++) acc[j][q] = 0ull;

    #pragma unroll
    for (int s = 0; s < 4; s++) {
        __syncthreads();
        for (int i = tid; i < 4096; i += 256) Wpc[i] = weffp[s * 4096 + i];
        __syncthreads();
        #pragma unroll 4
        for (int kp2 = 0; kp2 < 16; kp2++) {
            float4 x4[2];
            #pragma unroll
            for (int j = 0; j < 2; j++)
                x4[j] = *(const float4*)&Xs[s][(ng * 2 + j) * 64 + 4 * kp2];
            #pragma unroll
            for (int h = 0; h < 2; h++) {
                int kp = 2 * kp2 + h;
                unsigned long long w[4];
                #pragma unroll
                for (int q = 0; q < 4; q++)
                    w[q] = *(const unsigned long long*)&Wpc[(kp * 64 + cp + 16 * q) * 2];
                #pragma unroll
                for (int j = 0; j < 2; j++) {
                    unsigned long long x = ((const unsigned long long*)&x4[j])[h];
                    #pragma unroll
                    for (int q = 0; q < 4; q++) FMA_F32X2(acc[j][q], x, w[q], acc[j][q]);
                }
            }
        }
    }
    __syncthreads();
    #pragma unroll
    for (int j = 0; j < 2; j++) {
        int node_l = ng * 2 + j;
        #pragma unroll
        for (int q = 0; q < 4; q++) {
            int col = cp + 16 * q;
            float z = x2lo(acc[j][q]) + x2hi(acc[j][q]) + bm1[col];
            Zs[node_l * 68 + col] = z > 0.f ? z : 0.f;
        }
    }
    __syncthreads();

    // layer 2: 64 outputs (32 nodes x 2)
    if (tid < 64) {
        int node = tid >> 1, jj = tid & 1;
        if (nb + node < n) {
            float sacc = bm2[jj];
            #pragma unroll 8
            for (int c = 0; c < 64; c++) sacc += Zs[node * 68 + c] * Wm2[c * 2 + jj];
            logits[(size_t)(nb + node) * 2 + jj] = sacc;
        }
    }
}

// ---------------- launch (fork-join overlap restored) ----------------
extern "C" void kernel_launch(void* const* d_in, const int* in_sizes, int n_in,
                              void* d_out, int out_size) {
    const float* x     = (const float*)d_in[0];
    const float* sim_x = (const float*)d_in[1];
    const int*   src   = (const int*)d_in[2];
    const int*   dst   = (const int*)d_in[3];
    const int*   ssrc  = (const int*)d_in[4];
    const int*   sdst  = (const int*)d_in[5];
    const float* W1o   = (const float*)d_in[6];
    const float* b1o   = (const float*)d_in[7];
    const float* W1s   = (const float*)d_in[8];
    const float* b1s   = (const float*)d_in[9];
    const float* Wm1   = (const float*)d_in[10];
    const float* bm1   = (const float*)d_in[11];
    const float* Wm2   = (const float*)d_in[12];
    const float* bm2   = (const float*)d_in[13];

    const int n = NN, ne = NE;

    float *fbuf, *dinv, *weff; __half* gh; int *cnt, *cur, *rs, *csr;
    cudaGetSymbolAddress((void**)&fbuf, d_fbuf);
    cudaGetSymbolAddress((void**)&gh,   d_gh);
    cudaGetSymbolAddress((void**)&dinv, d_dinv);
    cudaGetSymbolAddress((void**)&cnt,  d_cnt);
    cudaGetSymbolAddress((void**)&cur,  d_cur);
    cudaGetSymbolAddress((void**)&rs,   d_rs);
    cudaGetSymbolAddress((void**)&csr,  d_csr);
    cudaGetSymbolAddress((void**)&weff, d_weff);

    float*  f0base = fbuf + 0 * S;
    float*  f1base = fbuf + 2 * S;
    float*  f2base = fbuf + 4 * S;
    __half* gabase = gh;
    __half* gbbase = gh + 2 * S;

    static cudaStream_t sB = nullptr;
    static cudaEvent_t eStart = nullptr, eScan = nullptr, eB = nullptr;
    if (!sB) {
        cudaStreamCreateWithFlags(&sB, cudaStreamNonBlocking);
        cudaEventCreateWithFlags(&eStart, cudaEventDisableTiming);
        cudaEventCreateWithFlags(&eScan,  cudaEventDisableTiming);
        cudaEventCreateWithFlags(&eB,     cudaEventDisableTiming);
    }

    cudaEventRecord(eStart, 0);
    cudaStreamWaitEvent(sB, eStart, 0);

    // stream0: CSR build chain (cnt pre-zeroed by previous scan_k / static init)
    int ne4 = ne / 4;
    int eb4 = (2 * ne4 + 255) / 256;
    count_k<<<eb4, 256>>>((const int4*)dst, (const int4*)sdst, cnt, ne4);
    scan_k<<<2, 1024>>>(cnt, rs, dinv, cur, n);
    cudaEventRecord(eScan, 0);
    fill_k<<<eb4, 256>>>((const int4*)src, (const int4*)ssrc,
                         (const int4*)dst, (const int4*)sdst, cur, csr, ne4);

    // sB: gemm from t0 (input-only deps), prep, then scale after scan
    dim3 gg((n + 63) / 64, 2);
    gemm_relu_k<<<gg, 256, 0, sB>>>(x, sim_x, W1o, W1s, b1o, b1s, f0base, n);
    prep_k<<<64, 256, 0, sB>>>(Wm1, weff);
    cudaStreamWaitEvent(sB, eScan, 0);
    int total8 = (int)(2 * S / 8);
    scale_k<<<(total8 + 255) / 256, 256, 0, sB>>>((const float4*)f0base, dinv,
                                                  (uint4*)gabase, total8);
    cudaEventRecord(eB, sB);

    // join, then serial props + tail on stream0
    cudaStreamWaitEvent(0, eB, 0);
    int pb = (2 * n * 32 + 255) / 256;
    prop_k<<<pb, 256>>>(gabase, f0base, f1base, gbbase, dinv, rs, csr, n, 1);
    prop_k<<<pb, 256>>>(gbbase, f1base, f2base, nullptr, dinv, rs, csr, n, 0);

    float* out    = (float*)d_out;
    float* logits = out + (size_t)n * 384;
    tail_k<<<(n + 31) / 32, 256>>>(fbuf, weff, bm1, Wm2, bm2, out, logits, n);
}

// round 15
// speedup vs baseline: 1.1408x; 1.0371x over previous
#include <cuda_runtime.h>
#include <cuda_bf16.h>
#include <cuda_fp16.h>
#include <stdint.h>

#define NN 50000
#define NE 800000
#define INF 128
#define HID 64
#define S ((size_t)NN * HID)

// packed dual fp32 FMA (sm_103a)
#define FMA_F32X2(d, a, b, c) \
    asm("fma.rn.f32x2 %0, %1, %2, %3;" : "=l"(d) : "l"(a), "l"(b), "l"(c))

__device__ __forceinline__ float x2lo(unsigned long long v) {
    return __uint_as_float((unsigned)(v & 0xffffffffull));
}
__device__ __forceinline__ float x2hi(unsigned long long v) {
    return __uint_as_float((unsigned)(v >> 32));
}

// ---------------- scratch ----------------
// fbuf slots (each S floats): 0=fo0 1=fs0 2=fo1 3=fs1 4=fo2 5=fs2
__device__ float d_fbuf[(size_t)6 * NN * HID];
__device__ __align__(16) __half d_gh[(size_t)4 * NN * HID];
__device__ float d_dinv[2 * NN];
__device__ int   d_cnt [2 * NN];          // static-zero; scan_k re-zeroes each pass
__device__ int   d_cur [2 * NN];
__device__ int   d_rs  [2 * (NN + 1)];
__device__ int   d_csr [2 * NE];
__device__ float d_weff[16384];   // folded tail layer-1 weights, interleaved [kp][c][2]

// ---------------- degree histogram ----------------
__global__ void count_k(const int4* __restrict__ d0, const int4* __restrict__ d1,
                        int* __restrict__ cnt, int ne4) {
    int i = blockIdx.x * blockDim.x + threadIdx.x;
    if (i >= 2 * ne4) return;
    int b = (i >= ne4) ? 1 : 0;
    int4 v = b ? d1[i - ne4] : d0[i];
    int* c = cnt + b * NN;
    atomicAdd(&c[v.x], 1);
    atomicAdd(&c[v.y], 1);
    atomicAdd(&c[v.z], 1);
    atomicAdd(&c[v.w], 1);
}

// ---------------- exclusive scan + dinv + cur init; zeroes cnt for next replay ----------------
__global__ void scan_k(int* __restrict__ cntA, int* __restrict__ rsA,
                       float* __restrict__ dvA, int* __restrict__ curA, int n) {
    int*   cnt = cntA + blockIdx.x * NN;
    int*   rs  = rsA  + blockIdx.x * (NN + 1);
    float* dv  = dvA  + blockIdx.x * NN;
    int*   cur = curA + blockIdx.x * NN;
    __shared__ int wsum[32];
    __shared__ int carry_s;
    int tid = threadIdx.x, lane = tid & 31, wid = tid >> 5;
    if (tid == 0) carry_s = 0;
    __syncthreads();
    for (int base = 0; base < n; base += 1024) {
        int i = base + tid;
        int v = (i < n) ? cnt[i] : 0;
        int x = v;
        #pragma unroll
        for (int d = 1; d < 32; d <<= 1) {
            int t = __shfl_up_sync(0xffffffffu, x, d);
            if (lane >= d) x += t;
        }
        if (lane == 31) wsum[wid] = x;
        __syncthreads();
        if (wid == 0) {
            int w = wsum[lane];
            int y = w;
            #pragma unroll
            for (int d = 1; d < 32; d <<= 1) {
                int t = __shfl_up_sync(0xffffffffu, y, d);
                if (lane >= d) y += t;
            }
            wsum[lane] = y - w;
        }
        __syncthreads();
        int excl = x - v + wsum[wid] + carry_s;
        if (i < n) {
            rs[i]  = excl;
            cur[i] = excl;
            dv[i]  = rsqrtf((float)(v > 0 ? v : 1));
            cnt[i] = 0;                      // reset for next graph replay
        }
        __syncthreads();
        if (tid == 1023) carry_s = excl + v;
        __syncthreads();
    }
    if (threadIdx.x == 0) rs[n] = carry_s;
}

// ---------------- CSR fill ----------------
__global__ void fill_k(const int4* __restrict__ s0, const int4* __restrict__ s1,
                       const int4* __restrict__ d0, const int4* __restrict__ d1,
                       int* __restrict__ cur, int* __restrict__ csr, int ne4) {
    int i = blockIdx.x * blockDim.x + threadIdx.x;
    if (i >= 2 * ne4) return;
    int b = (i >= ne4) ? 1 : 0;
    int j = i - b * ne4;
    int4 dd = b ? d1[j] : d0[j];
    int4 sv = b ? s1[j] : s0[j];
    int* cu = cur + b * NN;
    int* cs = csr + (size_t)b * NE;
    cs[atomicAdd(&cu[dd.x], 1)] = sv.x;
    cs[atomicAdd(&cu[dd.y], 1)] = sv.y;
    cs[atomicAdd(&cu[dd.z], 1)] = sv.z;
    cs[atomicAdd(&cu[dd.w], 1)] = sv.w;
}

// ---------------- input GEMM + relu (chunked Xs; 4 CTAs/SM reg cap) ----------------
__global__ void __launch_bounds__(256, 4) gemm_relu_k(
        const float* __restrict__ X0, const float* __restrict__ X1,
        const float* __restrict__ W0g, const float* __restrict__ W1g,
        const float* __restrict__ b0, const float* __restrict__ b1,
        float* __restrict__ f0base, int n) {
    __shared__ float Xs[64 * 64];    // 16 KB (one 64-k chunk)
    __shared__ float Wpc[4096];      // 16 KB [32kp][64c][2]
    int by = blockIdx.y;
    const float* X = by ? X1 : X0;
    const float* W = by ? W1g : W0g;
    const float* b = by ? b1 : b0;
    float* H = f0base + (size_t)by * S;

    int tid = threadIdx.x;
    int cp = tid & 15;
    int ng = tid >> 4;        // 0..15, 4 nodes each
    int nb = blockIdx.x * 64;
    int nvalid = n - nb; if (nvalid > 64) nvalid = 64;

    unsigned long long acc[4][4];
    #pragma unroll
    for (int j = 0; j < 4; j++)
        #pragma unroll
        for (int q = 0; q < 4; q++) acc[j][q] = 0ull;

    #pragma unroll
    for (int ch = 0; ch < 2; ch++) {
        __syncthreads();
        for (int i4 = tid; i4 < 1024; i4 += 256) {
            int node = i4 >> 4, f = i4 & 15;
            float4 v = make_float4(0.f, 0.f, 0.f, 0.f);
            if (node < nvalid)
                v = *(const float4*)(X + (size_t)(nb + node) * 128 + ch * 64 + f * 4);
            ((float4*)Xs)[i4] = v;
        }
        for (int i = tid; i < 4096; i += 256) {
            int j = i & 1, c = (i >> 1) & 63, kp = i >> 7;
            Wpc[i] = W[(size_t)(ch * 64 + 2 * kp + j) * 64 + c];
        }
        __syncthreads();
        #pragma unroll 4
        for (int kp2 = 0; kp2 < 16; kp2++) {
            float4 x4[4];
            #pragma unroll
            for (int j = 0; j < 4; j++)
                x4[j] = *(const float4*)&Xs[(ng * 4 + j) * 64 + 4 * kp2];
            #pragma unroll
            for (int h = 0; h < 2; h++) {
                int kp = 2 * kp2 + h;
                unsigned long long w[4];
                #pragma unroll
                for (int q = 0; q < 4; q++)
                    w[q] = *(const unsigned long long*)&Wpc[(kp * 64 + cp + 16 * q) * 2];
                #pragma unroll
                for (int j = 0; j < 4; j++) {
                    unsigned long long x = ((const unsigned long long*)&x4[j])[h];
                    #pragma unroll
                    for (int q = 0; q < 4; q++) FMA_F32X2(acc[j][q], x, w[q], acc[j][q]);
                }
            }
        }
    }

    #pragma unroll
    for (int j = 0; j < 4; j++) {
        int node = nb + ng * 4 + j;
        if (node < n) {
            #pragma unroll
            for (int q = 0; q < 4; q++) {
                int col = cp + 16 * q;
                float v = x2lo(acc[j][q]) + x2hi(acc[j][q]) + b[col];
                H[(size_t)node * 64 + col] = v > 0.f ? v : 0.f;
            }
        }
    }
}

// ---------------- g(fp16) = H * dinv ----------------
__global__ void scale_k(const float4* __restrict__ H, const float* __restrict__ dinv_all,
                        uint4* __restrict__ G, int total) {
    int i = blockIdx.x * blockDim.x + threadIdx.x;
    if (i >= total) return;
    float dv = dinv_all[i >> 3];
    float4 a = H[2 * i], b = H[2 * i + 1];
    __half2 h0 = __floats2half2_rn(a.x * dv, a.y * dv);
    __half2 h1 = __floats2half2_rn(a.z * dv, a.w * dv);
    __half2 h2 = __floats2half2_rn(b.x * dv, b.y * dv);
    __half2 h3 = __floats2half2_rn(b.z * dv, b.w * dv);
    uint4 o;
    o.x = *(unsigned*)&h0; o.y = *(unsigned*)&h1;
    o.z = *(unsigned*)&h2; o.w = *(unsigned*)&h3;
    G[i] = o;
}

// ---------------- tail weight prep (combine-fold, interleaved) ----------------
__global__ void prep_k(const float* __restrict__ Wm1, float* __restrict__ weff) {
    int i = blockIdx.x * blockDim.x + threadIdx.x;
    if (i >= 16384) return;
    int j = i & 1, c = (i >> 1) & 63, kpg = i >> 7;   // kpg 0..127
    int s = kpg >> 5;
    int kk = 2 * (kpg & 31) + j;                     // 0..63 within segment
    float w0 = Wm1[kk * 64 + c];
    float w1 = Wm1[(64 + kk) * 64 + c];
    float w2 = Wm1[(128 + kk) * 64 + c];
    float v;
    if (s == 0)      v = 3.f * w0;
    else if (s == 1) v = -3.f * w0 + 3.f * w1;
    else if (s == 2) v = 0.75f * w0 - 1.5f * w1 + 0.75f * w2;
    else v = 4.f * (Wm1[(192 + kk) * 64 + c] + Wm1[(256 + kk) * 64 + c] +
                    Wm1[(320 + kk) * 64 + c]);
    weff[i] = v;
}

// ---------------- propagation: R11 measured-best gather (break loop) ----------------
__global__ void prop_k(const __half* __restrict__ gin, const float* __restrict__ fin,
                       float* __restrict__ fout, __half* __restrict__ gout,
                       const float* __restrict__ dinv_all, const int* __restrict__ rs_all,
                       const int* __restrict__ csr_all, int n, int writeG) {
    int gw = (blockIdx.x * blockDim.x + threadIdx.x) >> 5;
    int lane = threadIdx.x & 31;
    if (gw >= 2 * n) return;
    int b = (gw >= n) ? 1 : 0;
    int w = gw - b * n;
    const __half* gp  = gin + (size_t)b * S;
    const int*    rs  = rs_all + b * (NN + 1);
    const int*    csr = csr_all + (size_t)b * NE;
    int beg = rs[w], end = rs[w + 1];

    int grp = lane >> 3;          // edge slot within 4-edge batch
    int sub = lane & 7;           // 16-B piece within 128-B row

    float a[8];
    #pragma unroll
    for (int i = 0; i < 8; i++) a[i] = 0.f;

    for (int base = beg; base < end; base += 32) {
        int idx = base + lane;
        int sreg = (idx < end) ? __ldg(&csr[idx]) : 0;
        int cnt = end - base;
        if (cnt > 32) cnt = 32;
        #pragma unroll
        for (int tb = 0; tb < 8; tb++) {
            if (tb * 4 >= cnt) break;
            int t = tb * 4 + grp;
            int ss = __shfl_sync(0xffffffffu, sreg, t);
            if (t < cnt) {
                uint4 v = *(const uint4*)(gp + (size_t)ss * 64 + sub * 8);
                const __half2* h = (const __half2*)&v;
                #pragma unroll
                for (int q = 0; q < 4; q++) {
                    float2 f = __half22float2(h[q]);
                    a[2 * q]     += f.x;
                    a[2 * q + 1] += f.y;
                }
            }
        }
    }

    #pragma unroll
    for (int i = 0; i < 8; i++) {
        a[i] += __shfl_xor_sync(0xffffffffu, a[i], 8);
        a[i] += __shfl_xor_sync(0xffffffffu, a[i], 16);
    }

    if (lane < 8) {
        float dvv = dinv_all[b * NN + w];
        const float4* f4 = (const float4*)(fin + (size_t)b * S + (size_t)w * 64 + lane * 8);
        float4 fv0 = f4[0], fv1 = f4[1];
        float4 o0, o1;
        o0.x = fv0.x - a[0] * dvv;
        o0.y = fv0.y - a[1] * dvv;
        o0.z = fv0.z - a[2] * dvv;
        o0.w = fv0.w - a[3] * dvv;
        o1.x = fv1.x - a[4] * dvv;
        o1.y = fv1.y - a[5] * dvv;
        o1.z = fv1.z - a[6] * dvv;
        o1.w = fv1.w - a[7] * dvv;
        float4* fo = (float4*)(fout + (size_t)b * S + (size_t)w * 64 + lane * 8);
        fo[0] = o0;
        fo[1] = o1;
        if (writeG) {
            __half2 h0 = __floats2half2_rn(o0.x * dvv, o0.y * dvv);
            __half2 h1 = __floats2half2_rn(o0.z * dvv, o0.w * dvv);
            __half2 h2 = __floats2half2_rn(o1.x * dvv, o1.y * dvv);
            __half2 h3 = __floats2half2_rn(o1.z * dvv, o1.w * dvv);
            uint4 gv;
            gv.x = *(unsigned*)&h0; gv.y = *(unsigned*)&h1;
            gv.z = *(unsigned*)&h2; gv.w = *(unsigned*)&h3;
            *(uint4*)(gout + (size_t)b * S + (size_t)w * 64 + lane * 8) = gv;
        }
    }
}

// ---------------- fused tail: combine -> h_all + 2-layer MLP ----------------
__global__ void __launch_bounds__(256) tail_k(
        const float* __restrict__ fbuf, const float* __restrict__ weffp,
        const float* __restrict__ bm1, const float* __restrict__ Wm2,
        const float* __restrict__ bm2,
        float* __restrict__ out, float* __restrict__ logits, int n) {
    __shared__ float Xs[4][32 * 64];   // 32 KB
    __shared__ float Wpc[4096];        // 16 KB
    __shared__ float Zs[32 * 68];      // 8.5 KB
    int tid = threadIdx.x;
    int cp = tid & 15, ng = tid >> 4;  // ng 0..15, 2 nodes each
    int nb = blockIdx.x * 32;

    const float* fo0 = fbuf + 0 * S;
    const float* fs0 = fbuf + 1 * S;
    const float* fo1 = fbuf + 2 * S;
    const float* fs1 = fbuf + 3 * S;
    const float* fo2 = fbuf + 4 * S;
    const float* fs2 = fbuf + 5 * S;

    int lim4 = (n - nb) * 16;
    if (lim4 > 512) lim4 = 512;
    for (int i4 = tid; i4 < 512; i4 += 256) {
        float4 z = make_float4(0.f, 0.f, 0.f, 0.f);
        float4 v0 = z, v1 = z, v2 = z, vs = z;
        if (i4 < lim4) {
            size_t off = (size_t)nb * 16 + i4;
            v0 = ((const float4*)fo0)[off];
            v1 = ((const float4*)fo1)[off];
            v2 = ((const float4*)fo2)[off];
            float4 u0 = ((const float4*)fs0)[off];
            float4 u1 = ((const float4*)fs1)[off];
            float4 u2 = ((const float4*)fs2)[off];
            vs.x = u0.x + u1.x + u2.x;
            vs.y = u0.y + u1.y + u2.y;
            vs.z = u0.z + u1.z + u2.z;
            vs.w = u0.w + u1.w + u2.w;
        }
        ((float4*)Xs[0])[i4] = v0;
        ((float4*)Xs[1])[i4] = v1;
        ((float4*)Xs[2])[i4] = v2;
        ((float4*)Xs[3])[i4] = vs;
    }
    __syncthreads();

    // h_all write (float4): 32 nodes x 96 float4
    int limo4 = (n - nb) * 96;
    if (limo4 > 3072) limo4 = 3072;
    for (int i4 = tid; i4 < limo4; i4 += 256) {
        int node_l = i4 / 96;
        int c4 = i4 - node_l * 96;
        int seg = c4 >> 4, cc4 = c4 & 15;
        int xi4 = node_l * 16 + cc4;
        float4 v;
        if (seg == 0) {
            float4 a0 = ((const float4*)Xs[0])[xi4];
            float4 a1 = ((const float4*)Xs[1])[xi4];
            float4 a2 = ((const float4*)Xs[2])[xi4];
            v.x = 3.f * a0.x - 3.f * a1.x + 0.75f * a2.x;
            v.y = 3.f * a0.y - 3.f * a1.y + 0.75f * a2.y;
            v.z = 3.f * a0.z - 3.f * a1.z + 0.75f * a2.z;
            v.w = 3.f * a0.w - 3.f * a1.w + 0.75f * a2.w;
        } else if (seg == 1) {
            float4 a1 = ((const float4*)Xs[1])[xi4];
            float4 a2 = ((const float4*)Xs[2])[xi4];
            v.x = 3.f * a1.x - 1.5f * a2.x;
            v.y = 3.f * a1.y - 1.5f * a2.y;
            v.z = 3.f * a1.z - 1.5f * a2.z;
            v.w = 3.f * a1.w - 1.5f * a2.w;
        } else if (seg == 2) {
            float4 a2 = ((const float4*)Xs[2])[xi4];
            v.x = 0.75f * a2.x; v.y = 0.75f * a2.y;
            v.z = 0.75f * a2.z; v.w = 0.75f * a2.w;
        } else {
            float4 a3 = ((const float4*)Xs[3])[xi4];
            v.x = 4.f * a3.x; v.y = 4.f * a3.y;
            v.z = 4.f * a3.z; v.w = 4.f * a3.w;
        }
        ((float4*)(out + (size_t)nb * 384))[i4] = v;
    }

    // layer 1 (K = 4 x 64, folded weights on basis f0,f1,f2,ssum)
    unsigned long long acc[2][4];
    #pragma unroll
    for (int j = 0; j < 2; j++)
        #pragma unroll
        for (int q = 0; q < 4; q++) acc[j][q] = 0ull;

    #pragma unroll
    for (int s = 0; s < 4; s++) {
        __syncthreads();
        for (int i = tid; i < 4096; i += 256) Wpc[i] = weffp[s * 4096 + i];
        __syncthreads();
        #pragma unroll 4
        for (int kp2 = 0; kp2 < 16; kp2++) {
            float4 x4[2];
            #pragma unroll
            for (int j = 0; j < 2; j++)
                x4[j] = *(const float4*)&Xs[s][(ng * 2 + j) * 64 + 4 * kp2];
            #pragma unroll
            for (int h = 0; h < 2; h++) {
                int kp = 2 * kp2 + h;
                unsigned long long w[4];
                #pragma unroll
                for (int q = 0; q < 4; q++)
                    w[q] = *(const unsigned long long*)&Wpc[(kp * 64 + cp + 16 * q) * 2];
                #pragma unroll
                for (int j = 0; j < 2; j++) {
                    unsigned long long x = ((const unsigned long long*)&x4[j])[h];
                    #pragma unroll
                    for (int q = 0; q < 4; q++) FMA_F32X2(acc[j][q], x, w[q], acc[j][q]);
                }
            }
        }
    }
    __syncthreads();
    #pragma unroll
    for (int j = 0; j < 2; j++) {
        int node_l = ng * 2 + j;
        #pragma unroll
        for (int q = 0; q < 4; q++) {
            int col = cp + 16 * q;
            float z = x2lo(acc[j][q]) + x2hi(acc[j][q]) + bm1[col];
            Zs[node_l * 68 + col] = z > 0.f ? z : 0.f;
        }
    }
    __syncthreads();

    // layer 2: 64 outputs (32 nodes x 2)
    if (tid < 64) {
        int node = tid >> 1, jj = tid & 1;
        if (nb + node < n) {
            float sacc = bm2[jj];
            #pragma unroll 8
            for (int c = 0; c < 64; c++) sacc += Zs[node * 68 + c] * Wm2[c * 2 + jj];
            logits[(size_t)(nb + node) * 2 + jj] = sacc;
        }
    }
}

// ---------------- launch (fork-join; prep off the join path) ----------------
extern "C" void kernel_launch(void* const* d_in, const int* in_sizes, int n_in,
                              void* d_out, int out_size) {
    const float* x     = (const float*)d_in[0];
    const float* sim_x = (const float*)d_in[1];
    const int*   src   = (const int*)d_in[2];
    const int*   dst   = (const int*)d_in[3];
    const int*   ssrc  = (const int*)d_in[4];
    const int*   sdst  = (const int*)d_in[5];
    const float* W1o   = (const float*)d_in[6];
    const float* b1o   = (const float*)d_in[7];
    const float* W1s   = (const float*)d_in[8];
    const float* b1s   = (const float*)d_in[9];
    const float* Wm1   = (const float*)d_in[10];
    const float* bm1   = (const float*)d_in[11];
    const float* Wm2   = (const float*)d_in[12];
    const float* bm2   = (const float*)d_in[13];

    const int n = NN, ne = NE;

    float *fbuf, *dinv, *weff; __half* gh; int *cnt, *cur, *rs, *csr;
    cudaGetSymbolAddress((void**)&fbuf, d_fbuf);
    cudaGetSymbolAddress((void**)&gh,   d_gh);
    cudaGetSymbolAddress((void**)&dinv, d_dinv);
    cudaGetSymbolAddress((void**)&cnt,  d_cnt);
    cudaGetSymbolAddress((void**)&cur,  d_cur);
    cudaGetSymbolAddress((void**)&rs,   d_rs);
    cudaGetSymbolAddress((void**)&csr,  d_csr);
    cudaGetSymbolAddress((void**)&weff, d_weff);

    float*  f0base = fbuf + 0 * S;
    float*  f1base = fbuf + 2 * S;
    float*  f2base = fbuf + 4 * S;
    __half* gabase = gh;
    __half* gbbase = gh + 2 * S;

    static cudaStream_t sB = nullptr;
    static cudaEvent_t eStart = nullptr, eScan = nullptr, eB = nullptr, ePrep = nullptr;
    if (!sB) {
        cudaStreamCreateWithFlags(&sB, cudaStreamNonBlocking);
        cudaEventCreateWithFlags(&eStart, cudaEventDisableTiming);
        cudaEventCreateWithFlags(&eScan,  cudaEventDisableTiming);
        cudaEventCreateWithFlags(&eB,     cudaEventDisableTiming);
        cudaEventCreateWithFlags(&ePrep,  cudaEventDisableTiming);
    }

    cudaEventRecord(eStart, 0);
    cudaStreamWaitEvent(sB, eStart, 0);

    // stream0: CSR build chain (cnt pre-zeroed by previous scan_k / static init)
    int ne4 = ne / 4;
    int eb4 = (2 * ne4 + 255) / 256;
    count_k<<<eb4, 256>>>((const int4*)dst, (const int4*)sdst, cnt, ne4);
    scan_k<<<2, 1024>>>(cnt, rs, dinv, cur, n);
    cudaEventRecord(eScan, 0);
    fill_k<<<eb4, 256>>>((const int4*)src, (const int4*)ssrc,
                         (const int4*)dst, (const int4*)sdst, cur, csr, ne4);

    // sB: gemm from t0 (input-only deps), then scale after scan; join = scale done
    dim3 gg((n + 63) / 64, 2);
    gemm_relu_k<<<gg, 256, 0, sB>>>(x, sim_x, W1o, W1s, b1o, b1s, f0base, n);
    cudaStreamWaitEvent(sB, eScan, 0);
    int total8 = (int)(2 * S / 8);
    scale_k<<<(total8 + 255) / 256, 256, 0, sB>>>((const float4*)f0base, dinv,
                                                  (uint4*)gabase, total8);
    cudaEventRecord(eB, sB);

    // prep overlaps the props (off the join path); only tail waits on it
    prep_k<<<64, 256, 0, sB>>>(Wm1, weff);
    cudaEventRecord(ePrep, sB);

    // join, then serial props + tail on stream0
    cudaStreamWaitEvent(0, eB, 0);
    int pb = (2 * n * 32 + 255) / 256;
    prop_k<<<pb, 256>>>(gabase, f0base, f1base, gbbase, dinv, rs, csr, n, 1);
    prop_k<<<pb, 256>>>(gbbase, f1base, f2base, nullptr, dinv, rs, csr, n, 0);

    cudaStreamWaitEvent(0, ePrep, 0);
    float* out    = (float*)d_out;
    float* logits = out + (size_t)n * 384;
    tail_k<<<(n + 31) / 32, 256>>>(fbuf, weff, bm1, Wm2, bm2, out, logits, n);
}

// round 16
// speedup vs baseline: 1.2612x; 1.1056x over previous
#include <cuda_runtime.h>
#include <cuda_bf16.h>
#include <cuda_fp16.h>
#include <mma.h>
#include <stdint.h>

using namespace nvcuda;

#define NN 50000
#define NE 800000
#define INF 128
#define HID 64
#define S ((size_t)NN * HID)

// packed dual fp32 FMA (sm_103a)
#define FMA_F32X2(d, a, b, c) \
    asm("fma.rn.f32x2 %0, %1, %2, %3;" : "=l"(d) : "l"(a), "l"(b), "l"(c))

__device__ __forceinline__ float x2lo(unsigned long long v) {
    return __uint_as_float((unsigned)(v & 0xffffffffull));
}
__device__ __forceinline__ float x2hi(unsigned long long v) {
    return __uint_as_float((unsigned)(v >> 32));
}

// ---------------- scratch ----------------
// fbuf slots (each S floats): 0=fo0 1=fs0 2=fo1 3=fs1 4=fo2 5=fs2(=ssum_s)
__device__ float d_fbuf[(size_t)6 * NN * HID];
__device__ __align__(16) __half d_gh[(size_t)4 * NN * HID];
__device__ float d_dinv[2 * NN];
__device__ int   d_cnt [2 * NN];          // static-zero; scan_k re-zeroes each pass
__device__ int   d_cur [2 * NN];
__device__ int   d_rs  [2 * (NN + 1)];
__device__ int   d_csr [2 * NE];
__device__ float d_weff[16384];   // folded tail layer-1 weights, interleaved [kp][c][2]

// ---------------- degree histogram ----------------
__global__ void count_k(const int4* __restrict__ d0, const int4* __restrict__ d1,
                        int* __restrict__ cnt, int ne4) {
    int i = blockIdx.x * blockDim.x + threadIdx.x;
    if (i >= 2 * ne4) return;
    int b = (i >= ne4) ? 1 : 0;
    int4 v = b ? d1[i - ne4] : d0[i];
    int* c = cnt + b * NN;
    atomicAdd(&c[v.x], 1);
    atomicAdd(&c[v.y], 1);
    atomicAdd(&c[v.z], 1);
    atomicAdd(&c[v.w], 1);
}

// ---------------- exclusive scan + dinv + cur init; zeroes cnt for next replay ----------------
__global__ void scan_k(int* __restrict__ cntA, int* __restrict__ rsA,
                       float* __restrict__ dvA, int* __restrict__ curA, int n) {
    int*   cnt = cntA + blockIdx.x * NN;
    int*   rs  = rsA  + blockIdx.x * (NN + 1);
    float* dv  = dvA  + blockIdx.x * NN;
    int*   cur = curA + blockIdx.x * NN;
    __shared__ int wsum[32];
    __shared__ int carry_s;
    int tid = threadIdx.x, lane = tid & 31, wid = tid >> 5;
    if (tid == 0) carry_s = 0;
    __syncthreads();
    for (int base = 0; base < n; base += 1024) {
        int i = base + tid;
        int v = (i < n) ? cnt[i] : 0;
        int x = v;
        #pragma unroll
        for (int d = 1; d < 32; d <<= 1) {
            int t = __shfl_up_sync(0xffffffffu, x, d);
            if (lane >= d) x += t;
        }
        if (lane == 31) wsum[wid] = x;
        __syncthreads();
        if (wid == 0) {
            int w = wsum[lane];
            int y = w;
            #pragma unroll
            for (int d = 1; d < 32; d <<= 1) {
                int t = __shfl_up_sync(0xffffffffu, y, d);
                if (lane >= d) y += t;
            }
            wsum[lane] = y - w;
        }
        __syncthreads();
        int excl = x - v + wsum[wid] + carry_s;
        if (i < n) {
            rs[i]  = excl;
            cur[i] = excl;
            dv[i]  = rsqrtf((float)(v > 0 ? v : 1));
            cnt[i] = 0;                      // reset for next graph replay
        }
        __syncthreads();
        if (tid == 1023) carry_s = excl + v;
        __syncthreads();
    }
    if (threadIdx.x == 0) rs[n] = carry_s;
}

// ---------------- CSR fill ----------------
__global__ void fill_k(const int4* __restrict__ s0, const int4* __restrict__ s1,
                       const int4* __restrict__ d0, const int4* __restrict__ d1,
                       int* __restrict__ cur, int* __restrict__ csr, int ne4) {
    int i = blockIdx.x * blockDim.x + threadIdx.x;
    if (i >= 2 * ne4) return;
    int b = (i >= ne4) ? 1 : 0;
    int j = i - b * ne4;
    int4 dd = b ? d1[j] : d0[j];
    int4 sv = b ? s1[j] : s0[j];
    int* cu = cur + b * NN;
    int* cs = csr + (size_t)b * NE;
    cs[atomicAdd(&cu[dd.x], 1)] = sv.x;
    cs[atomicAdd(&cu[dd.y], 1)] = sv.y;
    cs[atomicAdd(&cu[dd.z], 1)] = sv.z;
    cs[atomicAdd(&cu[dd.w], 1)] = sv.w;
}

// ---------------- input GEMM + relu via fp16 wmma (HMMA, fp32 accum) ----------------
// 64 nodes x 64 cols per block, 256 thr (8 warps); warp w -> rows (w>>1)*16, cols (w&1)*32.
__global__ void __launch_bounds__(256) gemm_relu_k(
        const float* __restrict__ X0, const float* __restrict__ X1,
        const float* __restrict__ W0g, const float* __restrict__ W1g,
        const float* __restrict__ b0, const float* __restrict__ b1,
        float* __restrict__ f0base, int n) {
    __shared__ __half Xh[64][136];     // 17408 B (X tile, fp16, pad 8)
    __shared__ __half Wh[128][72];     // 18432 B (W tile, fp16, pad 8)
    float* Cs = (float*)&Xh[0][0];     // overlay: 64 x 68 floats = 17408 B

    int by = blockIdx.y;
    const float* X = by ? X1 : X0;
    const float* W = by ? W1g : W0g;
    const float* b = by ? b1 : b0;
    float* H = f0base + (size_t)by * S;

    int tid = threadIdx.x;
    int nb = blockIdx.x * 64;
    int nvalid = n - nb; if (nvalid > 64) nvalid = 64;

    // stage X (64x128) as fp16; 8 elems per iter
    for (int i = tid; i < 1024; i += 256) {
        int node = i >> 4, koff = (i & 15) * 8;
        float4 va = make_float4(0.f, 0.f, 0.f, 0.f), vb = va;
        if (node < nvalid) {
            const float4* p = (const float4*)(X + (size_t)(nb + node) * 128 + koff);
            va = p[0]; vb = p[1];
        }
        __half2* dsth = (__half2*)&Xh[node][koff];
        dsth[0] = __floats2half2_rn(va.x, va.y);
        dsth[1] = __floats2half2_rn(va.z, va.w);
        dsth[2] = __floats2half2_rn(vb.x, vb.y);
        dsth[3] = __floats2half2_rn(vb.z, vb.w);
    }
    // stage W (128x64) as fp16
    for (int i = tid; i < 1024; i += 256) {
        int k = i >> 3, c = (i & 7) * 8;
        const float4* p = (const float4*)(W + (size_t)k * 64 + c);
        float4 va = p[0], vb = p[1];
        __half2* dsth = (__half2*)&Wh[k][c];
        dsth[0] = __floats2half2_rn(va.x, va.y);
        dsth[1] = __floats2half2_rn(va.z, va.w);
        dsth[2] = __floats2half2_rn(vb.x, vb.y);
        dsth[3] = __floats2half2_rn(vb.z, vb.w);
    }
    __syncthreads();

    int w = tid >> 5;
    int rt = w >> 1;         // 0..3 (row tile)
    int ct = w & 1;          // 0..1 (2 col tiles of 16 each)

    wmma::fragment<wmma::accumulator, 16, 16, 16, float> acc0, acc1;
    wmma::fill_fragment(acc0, 0.f);
    wmma::fill_fragment(acc1, 0.f);

    #pragma unroll
    for (int kk = 0; kk < 8; kk++) {
        wmma::fragment<wmma::matrix_a, 16, 16, 16, __half, wmma::row_major> af;
        wmma::fragment<wmma::matrix_b, 16, 16, 16, __half, wmma::row_major> bf0, bf1;
        wmma::load_matrix_sync(af, &Xh[rt * 16][kk * 16], 136);
        wmma::load_matrix_sync(bf0, &Wh[kk * 16][ct * 32], 72);
        wmma::load_matrix_sync(bf1, &Wh[kk * 16][ct * 32 + 16], 72);
        wmma::mma_sync(acc0, af, bf0, acc0);
        wmma::mma_sync(acc1, af, bf1, acc1);
    }

    __syncthreads();   // done reading Xh; safe to overlay Cs
    wmma::store_matrix_sync(&Cs[(rt * 16) * 68 + ct * 32], acc0, 68, wmma::mem_row_major);
    wmma::store_matrix_sync(&Cs[(rt * 16) * 68 + ct * 32 + 16], acc1, 68, wmma::mem_row_major);
    __syncthreads();

    for (int i = tid; i < 4096; i += 256) {
        int node = i >> 6, c = i & 63;
        if (node < nvalid) {
            float v = Cs[node * 68 + c] + b[c];
            H[(size_t)(nb + node) * 64 + c] = v > 0.f ? v : 0.f;
        }
    }
}

// ---------------- g(fp16) = H * dinv ----------------
__global__ void scale_k(const float4* __restrict__ H, const float* __restrict__ dinv_all,
                        uint4* __restrict__ G, int total) {
    int i = blockIdx.x * blockDim.x + threadIdx.x;
    if (i >= total) return;
    float dv = dinv_all[i >> 3];
    float4 a = H[2 * i], b = H[2 * i + 1];
    __half2 h0 = __floats2half2_rn(a.x * dv, a.y * dv);
    __half2 h1 = __floats2half2_rn(a.z * dv, a.w * dv);
    __half2 h2 = __floats2half2_rn(b.x * dv, b.y * dv);
    __half2 h3 = __floats2half2_rn(b.z * dv, b.w * dv);
    uint4 o;
    o.x = *(unsigned*)&h0; o.y = *(unsigned*)&h1;
    o.z = *(unsigned*)&h2; o.w = *(unsigned*)&h3;
    G[i] = o;
}

// ---------------- tail weight prep (combine-fold, interleaved) ----------------
__global__ void prep_k(const float* __restrict__ Wm1, float* __restrict__ weff) {
    int i = blockIdx.x * blockDim.x + threadIdx.x;
    if (i >= 16384) return;
    int j = i & 1, c = (i >> 1) & 63, kpg = i >> 7;   // kpg 0..127
    int s = kpg >> 5;
    int kk = 2 * (kpg & 31) + j;                     // 0..63 within segment
    float w0 = Wm1[kk * 64 + c];
    float w1 = Wm1[(64 + kk) * 64 + c];
    float w2 = Wm1[(128 + kk) * 64 + c];
    float v;
    if (s == 0)      v = 3.f * w0;
    else if (s == 1) v = -3.f * w0 + 3.f * w1;
    else if (s == 2) v = 0.75f * w0 - 1.5f * w1 + 0.75f * w2;
    else v = 4.f * (Wm1[(192 + kk) * 64 + c] + Wm1[(256 + kk) * 64 + c] +
                    Wm1[(320 + kk) * 64 + c]);
    weff[i] = v;
}

// ---------------- propagation (R11 gather); step2 can emit Σf for sim branch ----------------
__global__ void prop_k(const __half* __restrict__ gin, const float* __restrict__ fin,
                       float* __restrict__ fout, __half* __restrict__ gout,
                       const float* __restrict__ f0in,
                       const float* __restrict__ dinv_all, const int* __restrict__ rs_all,
                       const int* __restrict__ csr_all, int n, int writeG, int sumS) {
    int gw = (blockIdx.x * blockDim.x + threadIdx.x) >> 5;
    int lane = threadIdx.x & 31;
    if (gw >= 2 * n) return;
    int b = (gw >= n) ? 1 : 0;
    int w = gw - b * n;
    const __half* gp  = gin + (size_t)b * S;
    const int*    rs  = rs_all + b * (NN + 1);
    const int*    csr = csr_all + (size_t)b * NE;
    int beg = rs[w], end = rs[w + 1];

    int grp = lane >> 3;          // edge slot within 4-edge batch
    int sub = lane & 7;           // 16-B piece within 128-B row

    float a[8];
    #pragma unroll
    for (int i = 0; i < 8; i++) a[i] = 0.f;

    for (int base = beg; base < end; base += 32) {
        int idx = base + lane;
        int sreg = (idx < end) ? __ldg(&csr[idx]) : 0;
        int cnt = end - base;
        if (cnt > 32) cnt = 32;
        #pragma unroll
        for (int tb = 0; tb < 8; tb++) {
            if (tb * 4 >= cnt) break;
            int t = tb * 4 + grp;
            int ss = __shfl_sync(0xffffffffu, sreg, t);
            if (t < cnt) {
                uint4 v = *(const uint4*)(gp + (size_t)ss * 64 + sub * 8);
                const __half2* h = (const __half2*)&v;
                #pragma unroll
                for (int q = 0; q < 4; q++) {
                    float2 f = __half22float2(h[q]);
                    a[2 * q]     += f.x;
                    a[2 * q + 1] += f.y;
                }
            }
        }
    }

    #pragma unroll
    for (int i = 0; i < 8; i++) {
        a[i] += __shfl_xor_sync(0xffffffffu, a[i], 8);
        a[i] += __shfl_xor_sync(0xffffffffu, a[i], 16);
    }

    if (lane < 8) {
        float dvv = dinv_all[b * NN + w];
        size_t roff = (size_t)b * S + (size_t)w * 64 + lane * 8;
        const float4* f4 = (const float4*)(fin + roff);
        float4 fv0 = f4[0], fv1 = f4[1];
        float4 o0, o1;
        o0.x = fv0.x - a[0] * dvv;
        o0.y = fv0.y - a[1] * dvv;
        o0.z = fv0.z - a[2] * dvv;
        o0.w = fv0.w - a[3] * dvv;
        o1.x = fv1.x - a[4] * dvv;
        o1.y = fv1.y - a[5] * dvv;
        o1.z = fv1.z - a[6] * dvv;
        o1.w = fv1.w - a[7] * dvv;
        float4 w0 = o0, w1 = o1;
        if (sumS && b == 1) {
            // emit f0 + f1 + f2 for the sim branch (tail reads one array instead of 3)
            const float4* f04 = (const float4*)(f0in + roff);
            float4 z0 = f04[0], z1 = f04[1];
            w0.x = z0.x + fv0.x + o0.x;
            w0.y = z0.y + fv0.y + o0.y;
            w0.z = z0.z + fv0.z + o0.z;
            w0.w = z0.w + fv0.w + o0.w;
            w1.x = z1.x + fv1.x + o1.x;
            w1.y = z1.y + fv1.y + o1.y;
            w1.z = z1.z + fv1.z + o1.z;
            w1.w = z1.w + fv1.w + o1.w;
        }
        float4* fo = (float4*)(fout + roff);
        fo[0] = w0;
        fo[1] = w1;
        if (writeG) {
            __half2 h0 = __floats2half2_rn(o0.x * dvv, o0.y * dvv);
            __half2 h1 = __floats2half2_rn(o0.z * dvv, o0.w * dvv);
            __half2 h2 = __floats2half2_rn(o1.x * dvv, o1.y * dvv);
            __half2 h3 = __floats2half2_rn(o1.z * dvv, o1.w * dvv);
            uint4 gv;
            gv.x = *(unsigned*)&h0; gv.y = *(unsigned*)&h1;
            gv.z = *(unsigned*)&h2; gv.w = *(unsigned*)&h3;
            *(uint4*)(gout + roff) = gv;
        }
    }
}

// ---------------- fused tail: combine -> h_all + 2-layer MLP ----------------
// reads fo0, fo1, fo2, fs2(=ssum_s) only
__global__ void __launch_bounds__(256) tail_k(
        const float* __restrict__ fbuf, const float* __restrict__ weffp,
        const float* __restrict__ bm1, const float* __restrict__ Wm2,
        const float* __restrict__ bm2,
        float* __restrict__ out, float* __restrict__ logits, int n) {
    __shared__ float Xs[4][32 * 64];   // 32 KB
    __shared__ float Wpc[4096];        // 16 KB
    __shared__ float Zs[32 * 68];      // 8.5 KB
    int tid = threadIdx.x;
    int cp = tid & 15, ng = tid >> 4;  // ng 0..15, 2 nodes each
    int nb = blockIdx.x * 32;

    const float* fo0  = fbuf + 0 * S;
    const float* fo1  = fbuf + 2 * S;
    const float* fo2  = fbuf + 4 * S;
    const float* ssum = fbuf + 5 * S;   // fs2 slot holds fs0+fs1+fs2

    int lim4 = (n - nb) * 16;
    if (lim4 > 512) lim4 = 512;
    for (int i4 = tid; i4 < 512; i4 += 256) {
        float4 z = make_float4(0.f, 0.f, 0.f, 0.f);
        float4 v0 = z, v1 = z, v2 = z, vs = z;
        if (i4 < lim4) {
            size_t off = (size_t)nb * 16 + i4;
            v0 = ((const float4*)fo0)[off];
            v1 = ((const float4*)fo1)[off];
            v2 = ((const float4*)fo2)[off];
            vs = ((const float4*)ssum)[off];
        }
        ((float4*)Xs[0])[i4] = v0;
        ((float4*)Xs[1])[i4] = v1;
        ((float4*)Xs[2])[i4] = v2;
        ((float4*)Xs[3])[i4] = vs;
    }
    __syncthreads();

    // h_all write (float4): 32 nodes x 96 float4
    int limo4 = (n - nb) * 96;
    if (limo4 > 3072) limo4 = 3072;
    for (int i4 = tid; i4 < limo4; i4 += 256) {
        int node_l = i4 / 96;
        int c4 = i4 - node_l * 96;
        int seg = c4 >> 4, cc4 = c4 & 15;
        int xi4 = node_l * 16 + cc4;
        float4 v;
        if (seg == 0) {
            float4 a0 = ((const float4*)Xs[0])[xi4];
            float4 a1 = ((const float4*)Xs[1])[xi4];
            float4 a2 = ((const float4*)Xs[2])[xi4];
            v.x = 3.f * a0.x - 3.f * a1.x + 0.75f * a2.x;
            v.y = 3.f * a0.y - 3.f * a1.y + 0.75f * a2.y;
            v.z = 3.f * a0.z - 3.f * a1.z + 0.75f * a2.z;
            v.w = 3.f * a0.w - 3.f * a1.w + 0.75f * a2.w;
        } else if (seg == 1) {
            float4 a1 = ((const float4*)Xs[1])[xi4];
            float4 a2 = ((const float4*)Xs[2])[xi4];
            v.x = 3.f * a1.x - 1.5f * a2.x;
            v.y = 3.f * a1.y - 1.5f * a2.y;
            v.z = 3.f * a1.z - 1.5f * a2.z;
            v.w = 3.f * a1.w - 1.5f * a2.w;
        } else if (seg == 2) {
            float4 a2 = ((const float4*)Xs[2])[xi4];
            v.x = 0.75f * a2.x; v.y = 0.75f * a2.y;
            v.z = 0.75f * a2.z; v.w = 0.75f * a2.w;
        } else {
            float4 a3 = ((const float4*)Xs[3])[xi4];
            v.x = 4.f * a3.x; v.y = 4.f * a3.y;
            v.z = 4.f * a3.z; v.w = 4.f * a3.w;
        }
        ((float4*)(out + (size_t)nb * 384))[i4] = v;
    }

    // layer 1 (K = 4 x 64, folded weights on basis f0,f1,f2,ssum)
    unsigned long long acc[2][4];
    #pragma unroll
    for (int j = 0; j < 2; j++)
        #pragma unroll
        for (int q = 0; q < 4; q++) acc[j][q] = 0ull;

    #pragma unroll
    for (int s = 0; s < 4; s++) {
        __syncthreads();
        for (int i = tid; i < 4096; i += 256) Wpc[i] = weffp[s * 4096 + i];
        __syncthreads();
        #pragma unroll 4
        for (int kp2 = 0; kp2 < 16; kp2++) {
            float4 x4[2];
            #pragma unroll
            for (int j = 0; j < 2; j++)
                x4[j] = *(const float4*)&Xs[s][(ng * 2 + j) * 64 + 4 * kp2];
            #pragma unroll
            for (int h = 0; h < 2; h++) {
                int kp = 2 * kp2 + h;
                unsigned long long w[4];
                #pragma unroll
                for (int q = 0; q < 4; q++)
                    w[q] = *(const unsigned long long*)&Wpc[(kp * 64 + cp + 16 * q) * 2];
                #pragma unroll
                for (int j = 0; j < 2; j++) {
                    unsigned long long x = ((const unsigned long long*)&x4[j])[h];
                    #pragma unroll
                    for (int q = 0; q < 4; q++) FMA_F32X2(acc[j][q], x, w[q], acc[j][q]);
                }
            }
        }
    }
    __syncthreads();
    #pragma unroll
    for (int j = 0; j < 2; j++) {
        int node_l = ng * 2 + j;
        #pragma unroll
        for (int q = 0; q < 4; q++) {
            int col = cp + 16 * q;
            float z = x2lo(acc[j][q]) + x2hi(acc[j][q]) + bm1[col];
            Zs[node_l * 68 + col] = z > 0.f ? z : 0.f;
        }
    }
    __syncthreads();

    // layer 2: 64 outputs (32 nodes x 2)
    if (tid < 64) {
        int node = tid >> 1, jj = tid & 1;
        if (nb + node < n) {
            float sacc = bm2[jj];
            #pragma unroll 8
            for (int c = 0; c < 64; c++) sacc += Zs[node * 68 + c] * Wm2[c * 2 + jj];
            logits[(size_t)(nb + node) * 2 + jj] = sacc;
        }
    }
}

// ---------------- launch (fork-join; prep off the join path) ----------------
extern "C" void kernel_launch(void* const* d_in, const int* in_sizes, int n_in,
                              void* d_out, int out_size) {
    const float* x     = (const float*)d_in[0];
    const float* sim_x = (const float*)d_in[1];
    const int*   src   = (const int*)d_in[2];
    const int*   dst   = (const int*)d_in[3];
    const int*   ssrc  = (const int*)d_in[4];
    const int*   sdst  = (const int*)d_in[5];
    const float* W1o   = (const float*)d_in[6];
    const float* b1o   = (const float*)d_in[7];
    const float* W1s   = (const float*)d_in[8];
    const float* b1s   = (const float*)d_in[9];
    const float* Wm1   = (const float*)d_in[10];
    const float* bm1   = (const float*)d_in[11];
    const float* Wm2   = (const float*)d_in[12];
    const float* bm2   = (const float*)d_in[13];

    const int n = NN, ne = NE;

    float *fbuf, *dinv, *weff; __half* gh; int *cnt, *cur, *rs, *csr;
    cudaGetSymbolAddress((void**)&fbuf, d_fbuf);
    cudaGetSymbolAddress((void**)&gh,   d_gh);
    cudaGetSymbolAddress((void**)&dinv, d_dinv);
    cudaGetSymbolAddress((void**)&cnt,  d_cnt);
    cudaGetSymbolAddress((void**)&cur,  d_cur);
    cudaGetSymbolAddress((void**)&rs,   d_rs);
    cudaGetSymbolAddress((void**)&csr,  d_csr);
    cudaGetSymbolAddress((void**)&weff, d_weff);

    float*  f0base = fbuf + 0 * S;
    float*  f1base = fbuf + 2 * S;
    float*  f2base = fbuf + 4 * S;
    __half* gabase = gh;
    __half* gbbase = gh + 2 * S;

    static cudaStream_t sB = nullptr;
    static cudaEvent_t eStart = nullptr, eScan = nullptr, eB = nullptr, ePrep = nullptr;
    if (!sB) {
        cudaStreamCreateWithFlags(&sB, cudaStreamNonBlocking);
        cudaEventCreateWithFlags(&eStart, cudaEventDisableTiming);
        cudaEventCreateWithFlags(&eScan,  cudaEventDisableTiming);
        cudaEventCreateWithFlags(&eB,     cudaEventDisableTiming);
        cudaEventCreateWithFlags(&ePrep,  cudaEventDisableTiming);
    }

    cudaEventRecord(eStart, 0);
    cudaStreamWaitEvent(sB, eStart, 0);

    // stream0: CSR build chain (cnt pre-zeroed by previous scan_k / static init)
    int ne4 = ne / 4;
    int eb4 = (2 * ne4 + 255) / 256;
    count_k<<<eb4, 256>>>((const int4*)dst, (const int4*)sdst, cnt, ne4);
    scan_k<<<2, 1024>>>(cnt, rs, dinv, cur, n);
    cudaEventRecord(eScan, 0);
    fill_k<<<eb4, 256>>>((const int4*)src, (const int4*)ssrc,
                         (const int4*)dst, (const int4*)sdst, cur, csr, ne4);

    // sB: wmma gemm from t0 (input-only deps), then scale after scan; join = scale done
    dim3 gg((n + 63) / 64, 2);
    gemm_relu_k<<<gg, 256, 0, sB>>>(x, sim_x, W1o, W1s, b1o, b1s, f0base, n);
    cudaStreamWaitEvent(sB, eScan, 0);
    int total8 = (int)(2 * S / 8);
    scale_k<<<(total8 + 255) / 256, 256, 0, sB>>>((const float4*)f0base, dinv,
                                                  (uint4*)gabase, total8);
    cudaEventRecord(eB, sB);

    // prep overlaps the props (off the join path); only tail waits on it
    prep_k<<<64, 256, 0, sB>>>(Wm1, weff);
    cudaEventRecord(ePrep, sB);

    // join, then serial props + tail on stream0
    cudaStreamWaitEvent(0, eB, 0);
    int pb = (2 * n * 32 + 255) / 256;
    prop_k<<<pb, 256>>>(gabase, f0base, f1base, gbbase, nullptr,
                        dinv, rs, csr, n, 1, 0);
    prop_k<<<pb, 256>>>(gbbase, f1base, f2base, nullptr, f0base,
                        dinv, rs, csr, n, 0, 1);

    cudaStreamWaitEvent(0, ePrep, 0);
    float* out    = (float*)d_out;
    float* logits = out + (size_t)n * 384;
    tail_k<<<(n + 31) / 32, 256>>>(fbuf, weff, bm1, Wm2, bm2, out, logits, n);
}

// round 17
// speedup vs baseline: 1.2792x; 1.0142x over previous
#include <cuda_runtime.h>
#include <cuda_bf16.h>
#include <cuda_fp16.h>
#include <mma.h>
#include <stdint.h>

using namespace nvcuda;

#define NN 50000
#define NE 800000
#define INF 128
#define HID 64
#define S ((size_t)NN * HID)

// packed dual fp32 FMA (sm_103a)
#define FMA_F32X2(d, a, b, c) \
    asm("fma.rn.f32x2 %0, %1, %2, %3;" : "=l"(d) : "l"(a), "l"(b), "l"(c))

__device__ __forceinline__ float x2lo(unsigned long long v) {
    return __uint_as_float((unsigned)(v & 0xffffffffull));
}
__device__ __forceinline__ float x2hi(unsigned long long v) {
    return __uint_as_float((unsigned)(v >> 32));
}

// ---------------- scratch ----------------
// fp16 f-buffers (each S halfs): 0=fo0 1=fs0 2=fo1 3=fs1 4=fo2 5=ssum_s
__device__ __align__(16) __half d_fh[(size_t)6 * NN * HID];
__device__ float d_dinv[2 * NN];
__device__ int   d_cnt [2 * NN];          // static-zero; scan_k re-zeroes each pass
__device__ int   d_cur [2 * NN];
__device__ int   d_rs  [2 * (NN + 1)];
__device__ int   d_csr [2 * NE];
__device__ float d_weff[16384];   // folded tail layer-1 weights, interleaved [kp][c][2]

// ---------------- degree histogram ----------------
__global__ void count_k(const int4* __restrict__ d0, const int4* __restrict__ d1,
                        int* __restrict__ cnt, int ne4) {
    int i = blockIdx.x * blockDim.x + threadIdx.x;
    if (i >= 2 * ne4) return;
    int b = (i >= ne4) ? 1 : 0;
    int4 v = b ? d1[i - ne4] : d0[i];
    int* c = cnt + b * NN;
    atomicAdd(&c[v.x], 1);
    atomicAdd(&c[v.y], 1);
    atomicAdd(&c[v.z], 1);
    atomicAdd(&c[v.w], 1);
}

// ---------------- exclusive scan + dinv + cur init; zeroes cnt for next replay ----------------
__global__ void scan_k(int* __restrict__ cntA, int* __restrict__ rsA,
                       float* __restrict__ dvA, int* __restrict__ curA, int n) {
    int*   cnt = cntA + blockIdx.x * NN;
    int*   rs  = rsA  + blockIdx.x * (NN + 1);
    float* dv  = dvA  + blockIdx.x * NN;
    int*   cur = curA + blockIdx.x * NN;
    __shared__ int wsum[32];
    __shared__ int carry_s;
    int tid = threadIdx.x, lane = tid & 31, wid = tid >> 5;
    if (tid == 0) carry_s = 0;
    __syncthreads();
    for (int base = 0; base < n; base += 1024) {
        int i = base + tid;
        int v = (i < n) ? cnt[i] : 0;
        int x = v;
        #pragma unroll
        for (int d = 1; d < 32; d <<= 1) {
            int t = __shfl_up_sync(0xffffffffu, x, d);
            if (lane >= d) x += t;
        }
        if (lane == 31) wsum[wid] = x;
        __syncthreads();
        if (wid == 0) {
            int w = wsum[lane];
            int y = w;
            #pragma unroll
            for (int d = 1; d < 32; d <<= 1) {
                int t = __shfl_up_sync(0xffffffffu, y, d);
                if (lane >= d) y += t;
            }
            wsum[lane] = y - w;
        }
        __syncthreads();
        int excl = x - v + wsum[wid] + carry_s;
        if (i < n) {
            rs[i]  = excl;
            cur[i] = excl;
            dv[i]  = rsqrtf((float)(v > 0 ? v : 1));
            cnt[i] = 0;                      // reset for next graph replay
        }
        __syncthreads();
        if (tid == 1023) carry_s = excl + v;
        __syncthreads();
    }
    if (threadIdx.x == 0) rs[n] = carry_s;
}

// ---------------- CSR fill ----------------
__global__ void fill_k(const int4* __restrict__ s0, const int4* __restrict__ s1,
                       const int4* __restrict__ d0, const int4* __restrict__ d1,
                       int* __restrict__ cur, int* __restrict__ csr, int ne4) {
    int i = blockIdx.x * blockDim.x + threadIdx.x;
    if (i >= 2 * ne4) return;
    int b = (i >= ne4) ? 1 : 0;
    int j = i - b * ne4;
    int4 dd = b ? d1[j] : d0[j];
    int4 sv = b ? s1[j] : s0[j];
    int* cu = cur + b * NN;
    int* cs = csr + (size_t)b * NE;
    cs[atomicAdd(&cu[dd.x], 1)] = sv.x;
    cs[atomicAdd(&cu[dd.y], 1)] = sv.y;
    cs[atomicAdd(&cu[dd.z], 1)] = sv.z;
    cs[atomicAdd(&cu[dd.w], 1)] = sv.w;
}

// ---------------- input GEMM + relu via fp16 wmma; fp16 output ----------------
__global__ void __launch_bounds__(256) gemm_relu_k(
        const float* __restrict__ X0, const float* __restrict__ X1,
        const float* __restrict__ W0g, const float* __restrict__ W1g,
        const float* __restrict__ b0, const float* __restrict__ b1,
        __half* __restrict__ f0base, int n) {
    __shared__ __half Xh[64][136];     // 17408 B
    __shared__ __half Wh[128][72];     // 18432 B
    float* Cs = (float*)&Xh[0][0];     // overlay: 64 x 68 floats

    int by = blockIdx.y;
    const float* X = by ? X1 : X0;
    const float* W = by ? W1g : W0g;
    const float* b = by ? b1 : b0;
    __half* H = f0base + (size_t)by * S;

    int tid = threadIdx.x;
    int nb = blockIdx.x * 64;
    int nvalid = n - nb; if (nvalid > 64) nvalid = 64;

    for (int i = tid; i < 1024; i += 256) {
        int node = i >> 4, koff = (i & 15) * 8;
        float4 va = make_float4(0.f, 0.f, 0.f, 0.f), vb = va;
        if (node < nvalid) {
            const float4* p = (const float4*)(X + (size_t)(nb + node) * 128 + koff);
            va = p[0]; vb = p[1];
        }
        __half2* dsth = (__half2*)&Xh[node][koff];
        dsth[0] = __floats2half2_rn(va.x, va.y);
        dsth[1] = __floats2half2_rn(va.z, va.w);
        dsth[2] = __floats2half2_rn(vb.x, vb.y);
        dsth[3] = __floats2half2_rn(vb.z, vb.w);
    }
    for (int i = tid; i < 1024; i += 256) {
        int k = i >> 3, c = (i & 7) * 8;
        const float4* p = (const float4*)(W + (size_t)k * 64 + c);
        float4 va = p[0], vb = p[1];
        __half2* dsth = (__half2*)&Wh[k][c];
        dsth[0] = __floats2half2_rn(va.x, va.y);
        dsth[1] = __floats2half2_rn(va.z, va.w);
        dsth[2] = __floats2half2_rn(vb.x, vb.y);
        dsth[3] = __floats2half2_rn(vb.z, vb.w);
    }
    __syncthreads();

    int w = tid >> 5;
    int rt = w >> 1, ct = w & 1;

    wmma::fragment<wmma::accumulator, 16, 16, 16, float> acc0, acc1;
    wmma::fill_fragment(acc0, 0.f);
    wmma::fill_fragment(acc1, 0.f);

    #pragma unroll
    for (int kk = 0; kk < 8; kk++) {
        wmma::fragment<wmma::matrix_a, 16, 16, 16, __half, wmma::row_major> af;
        wmma::fragment<wmma::matrix_b, 16, 16, 16, __half, wmma::row_major> bf0, bf1;
        wmma::load_matrix_sync(af, &Xh[rt * 16][kk * 16], 136);
        wmma::load_matrix_sync(bf0, &Wh[kk * 16][ct * 32], 72);
        wmma::load_matrix_sync(bf1, &Wh[kk * 16][ct * 32 + 16], 72);
        wmma::mma_sync(acc0, af, bf0, acc0);
        wmma::mma_sync(acc1, af, bf1, acc1);
    }

    __syncthreads();
    wmma::store_matrix_sync(&Cs[(rt * 16) * 68 + ct * 32], acc0, 68, wmma::mem_row_major);
    wmma::store_matrix_sync(&Cs[(rt * 16) * 68 + ct * 32 + 16], acc1, 68, wmma::mem_row_major);
    __syncthreads();

    // epilogue: bias + relu, pack fp16, vector store (8 cols/thread)
    for (int i = tid; i < 512; i += 256) {
        int node = i >> 3, c8 = (i & 7) * 8;
        if (node < nvalid) {
            uint4 outv;
            __half2* oh = (__half2*)&outv;
            #pragma unroll
            for (int q = 0; q < 4; q++) {
                float va = Cs[node * 68 + c8 + 2 * q]     + b[c8 + 2 * q];
                float vb = Cs[node * 68 + c8 + 2 * q + 1] + b[c8 + 2 * q + 1];
                va = va > 0.f ? va : 0.f;
                vb = vb > 0.f ? vb : 0.f;
                oh[q] = __floats2half2_rn(va, vb);
            }
            *(uint4*)(H + (size_t)(nb + node) * 64 + c8) = outv;
        }
    }
}

// ---------------- tail weight prep (combine-fold, interleaved) ----------------
__global__ void prep_k(const float* __restrict__ Wm1, float* __restrict__ weff) {
    int i = blockIdx.x * blockDim.x + threadIdx.x;
    if (i >= 16384) return;
    int j = i & 1, c = (i >> 1) & 63, kpg = i >> 7;   // kpg 0..127
    int s = kpg >> 5;
    int kk = 2 * (kpg & 31) + j;
    float w0 = Wm1[kk * 64 + c];
    float w1 = Wm1[(64 + kk) * 64 + c];
    float w2 = Wm1[(128 + kk) * 64 + c];
    float v;
    if (s == 0)      v = 3.f * w0;
    else if (s == 1) v = -3.f * w0 + 3.f * w1;
    else if (s == 2) v = 0.75f * w0 - 1.5f * w1 + 0.75f * w2;
    else v = 4.f * (Wm1[(192 + kk) * 64 + c] + Wm1[(256 + kk) * 64 + c] +
                    Wm1[(320 + kk) * 64 + c]);
    weff[i] = v;
}

// ---------------- propagation: gather f[src]*dinv[src] (fp16 rows), fp16 I/O ----------------
// fout = fin - dinv * sum;  if sumS && b==1: fout = f0 + fin + (fin - dinv*sum)
__global__ void prop_k(const __half* __restrict__ fin, __half* __restrict__ fout,
                       const __half* __restrict__ f0in,
                       const float* __restrict__ dinv_all, const int* __restrict__ rs_all,
                       const int* __restrict__ csr_all, int n, int sumS) {
    int gw = (blockIdx.x * blockDim.x + threadIdx.x) >> 5;
    int lane = threadIdx.x & 31;
    if (gw >= 2 * n) return;
    int b = (gw >= n) ? 1 : 0;
    int w = gw - b * n;
    const __half* fp  = fin + (size_t)b * S;
    const float*  dvb = dinv_all + b * NN;
    const int*    rs  = rs_all + b * (NN + 1);
    const int*    csr = csr_all + (size_t)b * NE;
    int beg = rs[w], end = rs[w + 1];

    int grp = lane >> 3;          // edge slot within 4-edge batch
    int sub = lane & 7;           // 16-B piece within 128-B fp16 row

    float a[8];
    #pragma unroll
    for (int i = 0; i < 8; i++) a[i] = 0.f;

    for (int base = beg; base < end; base += 32) {
        int idx = base + lane;
        int sreg = 0;
        float dreg = 0.f;
        if (idx < end) {
            sreg = __ldg(&csr[idx]);
            dreg = __ldg(&dvb[sreg]);
        }
        int cnt = end - base;
        if (cnt > 32) cnt = 32;
        #pragma unroll
        for (int tb = 0; tb < 8; tb++) {
            if (tb * 4 >= cnt) break;
            int t = tb * 4 + grp;
            int ss  = __shfl_sync(0xffffffffu, sreg, t);
            float ds = __shfl_sync(0xffffffffu, dreg, t);
            if (t < cnt) {
                uint4 v = *(const uint4*)(fp + (size_t)ss * 64 + sub * 8);
                const __half2* h = (const __half2*)&v;
                #pragma unroll
                for (int q = 0; q < 4; q++) {
                    float2 f = __half22float2(h[q]);
                    a[2 * q]     = fmaf(f.x, ds, a[2 * q]);
                    a[2 * q + 1] = fmaf(f.y, ds, a[2 * q + 1]);
                }
            }
        }
    }

    #pragma unroll
    for (int i = 0; i < 8; i++) {
        a[i] += __shfl_xor_sync(0xffffffffu, a[i], 8);
        a[i] += __shfl_xor_sync(0xffffffffu, a[i], 16);
    }

    if (lane < 8) {
        float dvv = dvb[w];
        size_t roff = (size_t)b * S + (size_t)w * 64 + lane * 8;   // halfs
        uint4 fv = *(const uint4*)(fin + roff);
        const __half2* fh = (const __half2*)&fv;
        float o[8], fvf[8];
        #pragma unroll
        for (int q = 0; q < 4; q++) {
            float2 f = __half22float2(fh[q]);
            fvf[2 * q] = f.x; fvf[2 * q + 1] = f.y;
        }
        #pragma unroll
        for (int i = 0; i < 8; i++) o[i] = fvf[i] - a[i] * dvv;

        float wv[8];
        if (sumS && b == 1) {
            uint4 f0v = *(const uint4*)(f0in + roff);
            const __half2* f0h = (const __half2*)&f0v;
            #pragma unroll
            for (int q = 0; q < 4; q++) {
                float2 z = __half22float2(f0h[q]);
                wv[2 * q]     = z.x + fvf[2 * q]     + o[2 * q];
                wv[2 * q + 1] = z.y + fvf[2 * q + 1] + o[2 * q + 1];
            }
        } else {
            #pragma unroll
            for (int i = 0; i < 8; i++) wv[i] = o[i];
        }
        uint4 outv;
        __half2* oh = (__half2*)&outv;
        #pragma unroll
        for (int q = 0; q < 4; q++)
            oh[q] = __floats2half2_rn(wv[2 * q], wv[2 * q + 1]);
        *(uint4*)(fout + roff) = outv;
    }
}

// ---------------- fused tail: combine -> h_all (fp32) + 2-layer MLP ----------------
// reads fo0, fo1, fo2, ssum (fp16)
__global__ void __launch_bounds__(256) tail_k(
        const __half* __restrict__ fh, const float* __restrict__ weffp,
        const float* __restrict__ bm1, const float* __restrict__ Wm2,
        const float* __restrict__ bm2,
        float* __restrict__ out, float* __restrict__ logits, int n) {
    __shared__ float Xs[4][32 * 64];   // 32 KB
    __shared__ float Wpc[4096];        // 16 KB
    __shared__ float Zs[32 * 68];      // 8.5 KB
    int tid = threadIdx.x;
    int cp = tid & 15, ng = tid >> 4;
    int nb = blockIdx.x * 32;

    const __half* fo0  = fh + 0 * S;
    const __half* fo1  = fh + 2 * S;
    const __half* fo2  = fh + 4 * S;
    const __half* ssum = fh + 5 * S;

    // stage fp16 -> fp32: 32 nodes x 64 halfs = 256 uint4 per array
    int limh = (n - nb) * 8;           // valid uint4-groups (8 per node)
    if (limh > 256) limh = 256;
    for (int i8 = tid; i8 < 256; i8 += 256) {
        bool ok = i8 < limh;
        size_t off = (size_t)nb * 8 + i8;   // uint4 index into array
        const uint4* p0 = (const uint4*)fo0 + off;
        const uint4* p1 = (const uint4*)fo1 + off;
        const uint4* p2 = (const uint4*)fo2 + off;
        const uint4* p3 = (const uint4*)ssum + off;
        uint4 z4; z4.x = z4.y = z4.z = z4.w = 0u;   // 0u halves = 0.0
        uint4 v0 = ok ? *p0 : z4;
        uint4 v1 = ok ? *p1 : z4;
        uint4 v2 = ok ? *p2 : z4;
        uint4 v3 = ok ? *p3 : z4;
        int dsti = i8 * 8;                 // float index
        const __half2* h0 = (const __half2*)&v0;
        const __half2* h1 = (const __half2*)&v1;
        const __half2* h2 = (const __half2*)&v2;
        const __half2* h3 = (const __half2*)&v3;
        #pragma unroll
        for (int q = 0; q < 4; q++) {
            float2 f0 = __half22float2(h0[q]);
            float2 f1 = __half22float2(h1[q]);
            float2 f2 = __half22float2(h2[q]);
            float2 f3 = __half22float2(h3[q]);
            Xs[0][dsti + 2 * q] = f0.x; Xs[0][dsti + 2 * q + 1] = f0.y;
            Xs[1][dsti + 2 * q] = f1.x; Xs[1][dsti + 2 * q + 1] = f1.y;
            Xs[2][dsti + 2 * q] = f2.x; Xs[2][dsti + 2 * q + 1] = f2.y;
            Xs[3][dsti + 2 * q] = f3.x; Xs[3][dsti + 2 * q + 1] = f3.y;
        }
    }
    __syncthreads();

    // h_all write (float4): 32 nodes x 96 float4
    int limo4 = (n - nb) * 96;
    if (limo4 > 3072) limo4 = 3072;
    for (int i4 = tid; i4 < limo4; i4 += 256) {
        int node_l = i4 / 96;
        int c4 = i4 - node_l * 96;
        int seg = c4 >> 4, cc4 = c4 & 15;
        int xi4 = node_l * 16 + cc4;
        float4 v;
        if (seg == 0) {
            float4 a0 = ((const float4*)Xs[0])[xi4];
            float4 a1 = ((const float4*)Xs[1])[xi4];
            float4 a2 = ((const float4*)Xs[2])[xi4];
            v.x = 3.f * a0.x - 3.f * a1.x + 0.75f * a2.x;
            v.y = 3.f * a0.y - 3.f * a1.y + 0.75f * a2.y;
            v.z = 3.f * a0.z - 3.f * a1.z + 0.75f * a2.z;
            v.w = 3.f * a0.w - 3.f * a1.w + 0.75f * a2.w;
        } else if (seg == 1) {
            float4 a1 = ((const float4*)Xs[1])[xi4];
            float4 a2 = ((const float4*)Xs[2])[xi4];
            v.x = 3.f * a1.x - 1.5f * a2.x;
            v.y = 3.f * a1.y - 1.5f * a2.y;
            v.z = 3.f * a1.z - 1.5f * a2.z;
            v.w = 3.f * a1.w - 1.5f * a2.w;
        } else if (seg == 2) {
            float4 a2 = ((const float4*)Xs[2])[xi4];
            v.x = 0.75f * a2.x; v.y = 0.75f * a2.y;
            v.z = 0.75f * a2.z; v.w = 0.75f * a2.w;
        } else {
            float4 a3 = ((const float4*)Xs[3])[xi4];
            v.x = 4.f * a3.x; v.y = 4.f * a3.y;
            v.z = 4.f * a3.z; v.w = 4.f * a3.w;
        }
        ((float4*)(out + (size_t)nb * 384))[i4] = v;
    }

    // layer 1 (K = 4 x 64, folded weights on basis f0,f1,f2,ssum)
    unsigned long long acc[2][4];
    #pragma unroll
    for (int j = 0; j < 2; j++)
        #pragma unroll
        for (int q = 0; q < 4; q++) acc[j][q] = 0ull;

    #pragma unroll
    for (int s = 0; s < 4; s++) {
        __syncthreads();
        for (int i = tid; i < 4096; i += 256) Wpc[i] = weffp[s * 4096 + i];
        __syncthreads();
        #pragma unroll 4
        for (int kp2 = 0; kp2 < 16; kp2++) {
            float4 x4[2];
            #pragma unroll
            for (int j = 0; j < 2; j++)
                x4[j] = *(const float4*)&Xs[s][(ng * 2 + j) * 64 + 4 * kp2];
            #pragma unroll
            for (int h = 0; h < 2; h++) {
                int kp = 2 * kp2 + h;
                unsigned long long w[4];
                #pragma unroll
                for (int q = 0; q < 4; q++)
                    w[q] = *(const unsigned long long*)&Wpc[(kp * 64 + cp + 16 * q) * 2];
                #pragma unroll
                for (int j = 0; j < 2; j++) {
                    unsigned long long x = ((const unsigned long long*)&x4[j])[h];
                    #pragma unroll
                    for (int q = 0; q < 4; q++) FMA_F32X2(acc[j][q], x, w[q], acc[j][q]);
                }
            }
        }
    }
    __syncthreads();
    #pragma unroll
    for (int j = 0; j < 2; j++) {
        int node_l = ng * 2 + j;
        #pragma unroll
        for (int q = 0; q < 4; q++) {
            int col = cp + 16 * q;
            float z = x2lo(acc[j][q]) + x2hi(acc[j][q]) + bm1[col];
            Zs[node_l * 68 + col] = z > 0.f ? z : 0.f;
        }
    }
    __syncthreads();

    if (tid < 64) {
        int node = tid >> 1, jj = tid & 1;
        if (nb + node < n) {
            float sacc = bm2[jj];
            #pragma unroll 8
            for (int c = 0; c < 64; c++) sacc += Zs[node * 68 + c] * Wm2[c * 2 + jj];
            logits[(size_t)(nb + node) * 2 + jj] = sacc;
        }
    }
}

// ---------------- launch (fork-join; no scale kernel) ----------------
extern "C" void kernel_launch(void* const* d_in, const int* in_sizes, int n_in,
                              void* d_out, int out_size) {
    const float* x     = (const float*)d_in[0];
    const float* sim_x = (const float*)d_in[1];
    const int*   src   = (const int*)d_in[2];
    const int*   dst   = (const int*)d_in[3];
    const int*   ssrc  = (const int*)d_in[4];
    const int*   sdst  = (const int*)d_in[5];
    const float* W1o   = (const float*)d_in[6];
    const float* b1o   = (const float*)d_in[7];
    const float* W1s   = (const float*)d_in[8];
    const float* b1s   = (const float*)d_in[9];
    const float* Wm1   = (const float*)d_in[10];
    const float* bm1   = (const float*)d_in[11];
    const float* Wm2   = (const float*)d_in[12];
    const float* bm2   = (const float*)d_in[13];

    const int n = NN, ne = NE;

    float *dinv, *weff; __half* fh; int *cnt, *cur, *rs, *csr;
    cudaGetSymbolAddress((void**)&fh,   d_fh);
    cudaGetSymbolAddress((void**)&dinv, d_dinv);
    cudaGetSymbolAddress((void**)&cnt,  d_cnt);
    cudaGetSymbolAddress((void**)&cur,  d_cur);
    cudaGetSymbolAddress((void**)&rs,   d_rs);
    cudaGetSymbolAddress((void**)&csr,  d_csr);
    cudaGetSymbolAddress((void**)&weff, d_weff);

    __half* f0base = fh + 0 * S;
    __half* f1base = fh + 2 * S;
    __half* f2base = fh + 4 * S;

    static cudaStream_t sB = nullptr;
    static cudaEvent_t eStart = nullptr, eB = nullptr, ePrep = nullptr;
    if (!sB) {
        cudaStreamCreateWithFlags(&sB, cudaStreamNonBlocking);
        cudaEventCreateWithFlags(&eStart, cudaEventDisableTiming);
        cudaEventCreateWithFlags(&eB,     cudaEventDisableTiming);
        cudaEventCreateWithFlags(&ePrep,  cudaEventDisableTiming);
    }

    cudaEventRecord(eStart, 0);
    cudaStreamWaitEvent(sB, eStart, 0);

    // stream0: CSR build chain (cnt pre-zeroed by previous scan_k / static init)
    int ne4 = ne / 4;
    int eb4 = (2 * ne4 + 255) / 256;
    count_k<<<eb4, 256>>>((const int4*)dst, (const int4*)sdst, cnt, ne4);
    scan_k<<<2, 1024>>>(cnt, rs, dinv, cur, n);
    fill_k<<<eb4, 256>>>((const int4*)src, (const int4*)ssrc,
                         (const int4*)dst, (const int4*)sdst, cur, csr, ne4);

    // sB: wmma gemm from t0 (input-only deps); join = gemm done
    dim3 gg((n + 63) / 64, 2);
    gemm_relu_k<<<gg, 256, 0, sB>>>(x, sim_x, W1o, W1s, b1o, b1s, f0base, n);
    cudaEventRecord(eB, sB);

    // prep overlaps the props (off the join path); only tail waits on it
    prep_k<<<64, 256, 0, sB>>>(Wm1, weff);
    cudaEventRecord(ePrep, sB);

    // join, then serial props + tail on stream0
    cudaStreamWaitEvent(0, eB, 0);
    int pb = (2 * n * 32 + 255) / 256;
    prop_k<<<pb, 256>>>(f0base, f1base, nullptr, dinv, rs, csr, n, 0);
    prop_k<<<pb, 256>>>(f1base, f2base, f0base,  dinv, rs, csr, n, 1);

    cudaStreamWaitEvent(0, ePrep, 0);
    float* out    = (float*)d_out;
    float* logits = out + (size_t)n * 384;
    tail_k<<<(n + 31) / 32, 256>>>(fh, weff, bm1, Wm2, bm2, out, logits, n);
}